// round 3
// baseline (speedup 1.0000x reference)
#include <cuda_runtime.h>
#include <cuda_bf16.h>
#include <math.h>

// Shapes (fixed)
#define Bz 4
#define Sz 1024
#define Ez 1024
#define Hz 16
#define HDz 64
#define DFFz 4096
#define Mz (Bz*Sz)   // 4096 rows of activations

// ---------------- scratch (device globals; no allocations) ----------------
__device__ float g_nx [Mz*Ez];
__device__ float g_q  [Mz*Ez];
__device__ float g_k  [Mz*Ez];
__device__ float g_v  [Mz*Ez];
__device__ float g_o  [Mz*Ez];
__device__ float g_x1 [Mz*Ez];
__device__ float g_nx2[Mz*Ez];
__device__ float g_h1 [(size_t)Mz*DFFz];

// ---------------- helpers ----------------
__device__ __forceinline__ float gelu_f(float x) {
    const float c = 0.7978845608028654f; // sqrt(2/pi)
    float u = c * (x + 0.044715f * x * x * x);
    return 0.5f * x * (1.0f + tanhf(u));
}

// ---------------- LayerNorm (ddof=1, eps added to std) ----------------
// one block per row of 1024, 256 threads, float4 per thread
__global__ __launch_bounds__(256) void ln_kernel(const float* __restrict__ x,
                                                 const float* __restrict__ g,
                                                 const float* __restrict__ be,
                                                 float* __restrict__ y)
{
    __shared__ float red[32];
    int row = blockIdx.x;
    int tid = threadIdx.x;
    const float4* xr = (const float4*)(x + (size_t)row * Ez);
    float4 v = xr[tid];

    // sum
    float s = v.x + v.y + v.z + v.w;
    #pragma unroll
    for (int o = 16; o > 0; o >>= 1) s += __shfl_xor_sync(0xffffffffu, s, o);
    if ((tid & 31) == 0) red[tid >> 5] = s;
    __syncthreads();
    float t = (tid < 8) ? red[tid] : 0.0f;
    if (tid < 32) {
        #pragma unroll
        for (int o = 4; o > 0; o >>= 1) t += __shfl_xor_sync(0xffffffffu, t, o);
        if (tid == 0) red[0] = t;
    }
    __syncthreads();
    float mean = red[0] * (1.0f / Ez);
    __syncthreads();

    // sum of squared deviations
    float dx = v.x - mean, dy = v.y - mean, dz = v.z - mean, dw = v.w - mean;
    float sq = dx*dx + dy*dy + dz*dz + dw*dw;
    #pragma unroll
    for (int o = 16; o > 0; o >>= 1) sq += __shfl_xor_sync(0xffffffffu, sq, o);
    if ((tid & 31) == 0) red[tid >> 5] = sq;
    __syncthreads();
    float t2 = (tid < 8) ? red[tid] : 0.0f;
    if (tid < 32) {
        #pragma unroll
        for (int o = 4; o > 0; o >>= 1) t2 += __shfl_xor_sync(0xffffffffu, t2, o);
        if (tid == 0) red[0] = t2;
    }
    __syncthreads();
    float var = red[0] * (1.0f / (Ez - 1));   // ddof = 1
    float inv = 1.0f / (sqrtf(var) + 1e-8f);  // eps added to std

    float4 gg = ((const float4*)g)[tid];
    float4 bb = ((const float4*)be)[tid];
    float4 o4;
    o4.x = gg.x * dx * inv + bb.x;
    o4.y = gg.y * dy * inv + bb.y;
    o4.z = gg.z * dz * inv + bb.z;
    o4.w = gg.w * dw * inv + bb.w;
    ((float4*)(y + (size_t)row * Ez))[tid] = o4;
}

// ---------------- SGEMM: C[M,N] = A[M,K] * B[N,K]^T + bias[N] (+res) (+gelu) ----------------
#define BM 128
#define BN 128
#define BK 16

template<int ACT, bool RES>
__global__ __launch_bounds__(256) void gemm_kernel(const float* __restrict__ A,
                                                   const float* __restrict__ Bm,
                                                   const float* __restrict__ bias,
                                                   const float* __restrict__ res,
                                                   float* __restrict__ C,
                                                   int M, int N, int K)
{
    __shared__ float As[BK][BM];
    __shared__ float Bs[BK][BN];

    int tid = threadIdx.x;
    int ty = tid >> 4, tx = tid & 15;
    int rowBase = blockIdx.y * BM;
    int colBase = blockIdx.x * BN;

    float acc[8][8];
    #pragma unroll
    for (int i = 0; i < 8; i++)
        #pragma unroll
        for (int j = 0; j < 8; j++) acc[i][j] = 0.0f;

    for (int k0 = 0; k0 < K; k0 += BK) {
        #pragma unroll
        for (int l = 0; l < 2; l++) {
            int idx = tid * 2 + l;        // 0..511
            int r  = idx >> 2;            // 0..127
            int c4 = idx & 3;             // 0..3
            float4 va = *(const float4*)(A  + (size_t)(rowBase + r) * K + k0 + c4 * 4);
            As[c4*4+0][r] = va.x; As[c4*4+1][r] = va.y;
            As[c4*4+2][r] = va.z; As[c4*4+3][r] = va.w;
            float4 vb = *(const float4*)(Bm + (size_t)(colBase + r) * K + k0 + c4 * 4);
            Bs[c4*4+0][r] = vb.x; Bs[c4*4+1][r] = vb.y;
            Bs[c4*4+2][r] = vb.z; Bs[c4*4+3][r] = vb.w;
        }
        __syncthreads();

        #pragma unroll
        for (int k = 0; k < BK; k++) {
            float a[8], b[8];
            #pragma unroll
            for (int i = 0; i < 8; i++) a[i] = As[k][ty*8 + i];
            #pragma unroll
            for (int j = 0; j < 8; j++) b[j] = Bs[k][tx*8 + j];
            #pragma unroll
            for (int i = 0; i < 8; i++)
                #pragma unroll
                for (int j = 0; j < 8; j++) acc[i][j] += a[i] * b[j];
        }
        __syncthreads();
    }

    #pragma unroll
    for (int i = 0; i < 8; i++) {
        int m = rowBase + ty*8 + i;
        #pragma unroll
        for (int j = 0; j < 8; j++) {
            int n = colBase + tx*8 + j;
            float vv = acc[i][j] + bias[n];
            if (RES) vv += res[(size_t)m * N + n];
            if (ACT == 1) vv = gelu_f(vv);
            C[(size_t)m * N + n] = vv;
        }
    }
}

// ---------------- Fused attention ----------------
// grid: (S/64, H, B); 256 threads. Masked score = -0.01 (finite), scores bounded,
// so exp without max-subtraction is numerically safe. Unnormalized accumulate,
// divide by row-sum at the end.
__global__ __launch_bounds__(256) void attn_kernel(const float* __restrict__ Q,
                                                   const float* __restrict__ K,
                                                   const float* __restrict__ V,
                                                   const int* __restrict__ mask,
                                                   float* __restrict__ O)
{
    __shared__ float Qs[64][65];
    __shared__ float Ks[32][65];
    __shared__ float Vs[32][65];
    __shared__ float Ps[64][33];
    __shared__ float Red[64][17];

    int qt = blockIdx.x, h = blockIdx.y, b = blockIdx.z;
    int tid = threadIdx.x;
    int ty = tid >> 4, tx = tid & 15;
    int q0 = qt * 64;
    int r0 = ty * 4;      // 4 q-rows per thread
    int c0 = tx * 2;      // 2 k-cols per thread (score phase)
    int d0 = tx * 4;      // 4 d-cols per thread (PV phase)

    // load Q tile scaled by 1/sqrt(HD)
    for (int i = tid; i < 64 * 64; i += 256) {
        int r = i >> 6, d = i & 63;
        Qs[r][d] = Q[(size_t)(b*Sz + q0 + r) * Ez + h*HDz + d] * 0.125f;
    }

    float acc[4][4];
    #pragma unroll
    for (int i = 0; i < 4; i++)
        #pragma unroll
        for (int j = 0; j < 4; j++) acc[i][j] = 0.0f;
    float rs[4] = {0.f, 0.f, 0.f, 0.f};

    for (int k0 = 0; k0 < Sz; k0 += 32) {
        __syncthreads();   // prior PV reads of Ks/Vs/Ps complete
        for (int i = tid; i < 32 * 64; i += 256) {
            int r = i >> 6, d = i & 63;
            size_t gi = (size_t)(b*Sz + k0 + r) * Ez + h*HDz + d;
            Ks[r][d] = K[gi];
            Vs[r][d] = V[gi];
        }
        __syncthreads();

        // scores: rows r0..r0+3, cols c0..c0+1
        float sv[4][2];
        #pragma unroll
        for (int i = 0; i < 4; i++) { sv[i][0] = 0.f; sv[i][1] = 0.f; }
        #pragma unroll 8
        for (int d = 0; d < 64; d++) {
            float qa0 = Qs[r0+0][d], qa1 = Qs[r0+1][d], qa2 = Qs[r0+2][d], qa3 = Qs[r0+3][d];
            float kb0 = Ks[c0+0][d], kb1 = Ks[c0+1][d];
            sv[0][0] += qa0*kb0; sv[0][1] += qa0*kb1;
            sv[1][0] += qa1*kb0; sv[1][1] += qa1*kb1;
            sv[2][0] += qa2*kb0; sv[2][1] += qa2*kb1;
            sv[3][0] += qa3*kb0; sv[3][1] += qa3*kb1;
        }
        #pragma unroll
        for (int i = 0; i < 4; i++) {
            int gq = q0 + r0 + i;
            const int* mrow = mask + (size_t)(b*Sz + gq) * Sz + k0;
            #pragma unroll
            for (int j = 0; j < 2; j++) {
                int m = mrow[c0 + j];
                float s = m ? sv[i][j] : -0.01f;
                float p = __expf(s);
                rs[i] += p;
                Ps[r0+i][c0+j] = p;
            }
        }
        __syncthreads();

        // O += P * V  (rows r0.., cols d0..)
        #pragma unroll 4
        for (int kk = 0; kk < 32; kk++) {
            float p0 = Ps[r0+0][kk], p1 = Ps[r0+1][kk], p2 = Ps[r0+2][kk], p3 = Ps[r0+3][kk];
            float v0 = Vs[kk][d0+0], v1 = Vs[kk][d0+1], v2 = Vs[kk][d0+2], v3 = Vs[kk][d0+3];
            acc[0][0]+=p0*v0; acc[0][1]+=p0*v1; acc[0][2]+=p0*v2; acc[0][3]+=p0*v3;
            acc[1][0]+=p1*v0; acc[1][1]+=p1*v1; acc[1][2]+=p1*v2; acc[1][3]+=p1*v3;
            acc[2][0]+=p2*v0; acc[2][1]+=p2*v1; acc[2][2]+=p2*v2; acc[2][3]+=p2*v3;
            acc[3][0]+=p3*v0; acc[3][1]+=p3*v1; acc[3][2]+=p3*v2; acc[3][3]+=p3*v3;
        }
    }

    // row-sum reduction across tx
    __syncthreads();
    #pragma unroll
    for (int i = 0; i < 4; i++) Red[r0+i][tx] = rs[i];
    __syncthreads();
    float l[4];
    #pragma unroll
    for (int i = 0; i < 4; i++) {
        float t = 0.f;
        #pragma unroll
        for (int u = 0; u < 16; u++) t += Red[r0+i][u];
        l[i] = t;
    }

    // write out (layout [B,S,E], head h at cols h*64..): transpose-back is free
    #pragma unroll
    for (int i = 0; i < 4; i++) {
        float inv = 1.0f / l[i];
        #pragma unroll
        for (int j = 0; j < 4; j++) {
            O[(size_t)(b*Sz + q0 + r0 + i) * Ez + h*HDz + d0 + j] = acc[i][j] * inv;
        }
    }
}

// ---------------- launch ----------------
extern "C" void kernel_launch(void* const* d_in, const int* in_sizes, int n_in,
                              void* d_out, int out_size)
{
    const float* x   = (const float*)d_in[0];
    const int*   msk = (const int*)  d_in[1];
    const float* Wq  = (const float*)d_in[2];
    const float* bq  = (const float*)d_in[3];
    const float* Wk  = (const float*)d_in[4];
    const float* bk  = (const float*)d_in[5];
    const float* Wv  = (const float*)d_in[6];
    const float* bv  = (const float*)d_in[7];
    const float* Wo  = (const float*)d_in[8];
    const float* bo  = (const float*)d_in[9];
    const float* W1  = (const float*)d_in[10];
    const float* b1  = (const float*)d_in[11];
    const float* W2  = (const float*)d_in[12];
    const float* b2  = (const float*)d_in[13];
    const float* g1  = (const float*)d_in[14];
    const float* be1 = (const float*)d_in[15];
    const float* g2  = (const float*)d_in[16];
    const float* be2 = (const float*)d_in[17];
    float* out = (float*)d_out;

    float *nx, *q, *k, *v, *o, *x1, *nx2, *h1;
    cudaGetSymbolAddress((void**)&nx,  g_nx);
    cudaGetSymbolAddress((void**)&q,   g_q);
    cudaGetSymbolAddress((void**)&k,   g_k);
    cudaGetSymbolAddress((void**)&v,   g_v);
    cudaGetSymbolAddress((void**)&o,   g_o);
    cudaGetSymbolAddress((void**)&x1,  g_x1);
    cudaGetSymbolAddress((void**)&nx2, g_nx2);
    cudaGetSymbolAddress((void**)&h1,  g_h1);

    dim3 gE(Ez/BN,   Mz/BM);   // N=1024
    dim3 gF(DFFz/BN, Mz/BM);   // N=4096

    // 1) LN1
    ln_kernel<<<Mz, 256>>>(x, g1, be1, nx);
    // 2-4) Q, K, V projections
    gemm_kernel<0,false><<<gE, 256>>>(nx, Wq, bq, nullptr, q, Mz, Ez, Ez);
    gemm_kernel<0,false><<<gE, 256>>>(nx, Wk, bk, nullptr, k, Mz, Ez, Ez);
    gemm_kernel<0,false><<<gE, 256>>>(nx, Wv, bv, nullptr, v, Mz, Ez, Ez);
    // 5) attention
    attn_kernel<<<dim3(Sz/64, Hz, Bz), 256>>>(q, k, v, msk, o);
    // 6) output projection + residual
    gemm_kernel<0,true><<<gE, 256>>>(o, Wo, bo, x, x1, Mz, Ez, Ez);
    // 7) LN2
    ln_kernel<<<Mz, 256>>>(x1, g2, be2, nx2);
    // 8) FFN up + GELU
    gemm_kernel<1,false><<<gF, 256>>>(nx2, W1, b1, nullptr, h1, Mz, DFFz, Ez);
    // 9) FFN down + residual -> out
    gemm_kernel<0,true><<<gE, 256>>>(h1, W2, b2, x1, out, Mz, Ez, DFFz);
}

// round 4
// speedup vs baseline: 2.1060x; 2.1060x over previous
#include <cuda_runtime.h>
#include <cuda_bf16.h>
#include <math.h>

// Shapes (fixed)
#define Bz 4
#define Sz 1024
#define Ez 1024
#define Hz 16
#define HDz 64
#define DFFz 4096
#define Mz (Bz*Sz)   // 4096 rows of activations

// ---------------- scratch (device globals; no allocations) ----------------
__device__ float g_nx [Mz*Ez];
__device__ float g_q  [Mz*Ez];
__device__ float g_k  [Mz*Ez];
__device__ float g_v  [Mz*Ez];
__device__ float g_o  [Mz*Ez];
__device__ float g_x1 [Mz*Ez];
__device__ float g_nx2[Mz*Ez];
__device__ float g_h1 [(size_t)Mz*DFFz];

// ---------------- helpers ----------------
__device__ __forceinline__ float gelu_f(float x) {
    const float c = 0.7978845608028654f; // sqrt(2/pi)
    float u = c * (x + 0.044715f * x * x * x);
    return 0.5f * x * (1.0f + tanhf(u));
}

__device__ __forceinline__ unsigned f2tf32(float x) {
    unsigned r;
    asm("cvt.rna.tf32.f32 %0, %1;" : "=r"(r) : "f"(x));
    return r;
}

__device__ __forceinline__ void mma_tf32(float* c, const unsigned* a, const unsigned* b) {
    asm volatile(
        "mma.sync.aligned.m16n8k8.row.col.f32.tf32.tf32.f32 "
        "{%0,%1,%2,%3}, {%4,%5,%6,%7}, {%8,%9}, {%0,%1,%2,%3};\n"
        : "+f"(c[0]), "+f"(c[1]), "+f"(c[2]), "+f"(c[3])
        : "r"(a[0]), "r"(a[1]), "r"(a[2]), "r"(a[3]),
          "r"(b[0]), "r"(b[1]));
}

// ---------------- LayerNorm (ddof=1, eps added to std) ----------------
__global__ __launch_bounds__(256) void ln_kernel(const float* __restrict__ x,
                                                 const float* __restrict__ g,
                                                 const float* __restrict__ be,
                                                 float* __restrict__ y)
{
    __shared__ float red[32];
    int row = blockIdx.x;
    int tid = threadIdx.x;
    const float4* xr = (const float4*)(x + (size_t)row * Ez);
    float4 v = xr[tid];

    float s = v.x + v.y + v.z + v.w;
    #pragma unroll
    for (int o = 16; o > 0; o >>= 1) s += __shfl_xor_sync(0xffffffffu, s, o);
    if ((tid & 31) == 0) red[tid >> 5] = s;
    __syncthreads();
    float t = (tid < 8) ? red[tid] : 0.0f;
    if (tid < 32) {
        #pragma unroll
        for (int o = 4; o > 0; o >>= 1) t += __shfl_xor_sync(0xffffffffu, t, o);
        if (tid == 0) red[0] = t;
    }
    __syncthreads();
    float mean = red[0] * (1.0f / Ez);
    __syncthreads();

    float dx = v.x - mean, dy = v.y - mean, dz = v.z - mean, dw = v.w - mean;
    float sq = dx*dx + dy*dy + dz*dz + dw*dw;
    #pragma unroll
    for (int o = 16; o > 0; o >>= 1) sq += __shfl_xor_sync(0xffffffffu, sq, o);
    if ((tid & 31) == 0) red[tid >> 5] = sq;
    __syncthreads();
    float t2 = (tid < 8) ? red[tid] : 0.0f;
    if (tid < 32) {
        #pragma unroll
        for (int o = 4; o > 0; o >>= 1) t2 += __shfl_xor_sync(0xffffffffu, t2, o);
        if (tid == 0) red[0] = t2;
    }
    __syncthreads();
    float var = red[0] * (1.0f / (Ez - 1));
    float inv = 1.0f / (sqrtf(var) + 1e-8f);

    float4 gg = ((const float4*)g)[tid];
    float4 bb = ((const float4*)be)[tid];
    float4 o4;
    o4.x = gg.x * dx * inv + bb.x;
    o4.y = gg.y * dy * inv + bb.y;
    o4.z = gg.z * dz * inv + bb.z;
    o4.w = gg.w * dw * inv + bb.w;
    ((float4*)(y + (size_t)row * Ez))[tid] = o4;
}

// ---------------- TF32 tensor-core GEMM ----------------
// C[M,N] = A[M,K] * B[N,K]^T + bias[N] (+res) (+gelu)
// 128x128x32 tiles, 8 warps (4x2), warp tile 32x64 (2 m16-tiles x 8 n8-tiles)
#define BM 128
#define BN 128
#define BK 32
#define KST 36   // BK + 4 pad: conflict-free fragment loads

#define GEMM_SMEM (2*(BM+BN)*KST*4)

template<int ACT, bool RES>
__global__ __launch_bounds__(256) void gemm_tf32(const float* __restrict__ A,
                                                 const float* __restrict__ Bm,
                                                 const float* __restrict__ bias,
                                                 const float* __restrict__ res,
                                                 float* __restrict__ C,
                                                 int M, int N, int K)
{
    extern __shared__ float smem[];
    float* As = smem;                       // [2][BM][KST]
    float* Bs = smem + 2 * BM * KST;        // [2][BN][KST]

    const int tid  = threadIdx.x;
    const int warp = tid >> 5, lane = tid & 31;
    const int wm = warp >> 1, wn = warp & 1;   // 4 x 2 warp grid
    const int qr = lane >> 2, qt = lane & 3;   // quad row / quad thread
    const int rowBase = blockIdx.y * BM;
    const int colBase = blockIdx.x * BN;

    float acc[2][8][4];
    #pragma unroll
    for (int mi = 0; mi < 2; mi++)
        #pragma unroll
        for (int ni = 0; ni < 8; ni++)
            #pragma unroll
            for (int r = 0; r < 4; r++) acc[mi][ni][r] = 0.0f;

    // per-thread global load map: idx = l*256+tid; row = idx/8, c4 = idx%8
    float4 ra[4], rb[4];

    auto load_global = [&](int k0) {
        #pragma unroll
        for (int l = 0; l < 4; l++) {
            int idx = l * 256 + tid;
            int r = idx >> 3, c = idx & 7;
            ra[l] = *(const float4*)(A  + (size_t)(rowBase + r) * K + k0 + c * 4);
            rb[l] = *(const float4*)(Bm + (size_t)(colBase + r) * K + k0 + c * 4);
        }
    };
    auto store_smem = [&](int buf) {
        float* as = As + buf * BM * KST;
        float* bs = Bs + buf * BN * KST;
        #pragma unroll
        for (int l = 0; l < 4; l++) {
            int idx = l * 256 + tid;
            int r = idx >> 3, c = idx & 7;
            uint4 ua, ub;
            ua.x = f2tf32(ra[l].x); ua.y = f2tf32(ra[l].y);
            ua.z = f2tf32(ra[l].z); ua.w = f2tf32(ra[l].w);
            ub.x = f2tf32(rb[l].x); ub.y = f2tf32(rb[l].y);
            ub.z = f2tf32(rb[l].z); ub.w = f2tf32(rb[l].w);
            *(uint4*)(as + r * KST + c * 4) = ua;
            *(uint4*)(bs + r * KST + c * 4) = ub;
        }
    };

    const int T = K / BK;
    load_global(0);
    store_smem(0);
    __syncthreads();

    for (int t = 0; t < T; t++) {
        if (t + 1 < T) load_global((t + 1) * BK);

        const unsigned* as = (const unsigned*)(As + (t & 1) * BM * KST) + (wm * 32) * KST;
        const unsigned* bs = (const unsigned*)(Bs + (t & 1) * BN * KST) + (wn * 64) * KST;

        #pragma unroll
        for (int kk = 0; kk < BK; kk += 8) {
            unsigned af[2][4], bf[8][2];
            #pragma unroll
            for (int mi = 0; mi < 2; mi++) {
                int base = (mi * 16 + qr) * KST + kk + qt;
                af[mi][0] = as[base];
                af[mi][1] = as[base + 8 * KST];
                af[mi][2] = as[base + 4];
                af[mi][3] = as[base + 8 * KST + 4];
            }
            #pragma unroll
            for (int ni = 0; ni < 8; ni++) {
                int base = (ni * 8 + qr) * KST + kk + qt;
                bf[ni][0] = bs[base];
                bf[ni][1] = bs[base + 4];
            }
            #pragma unroll
            for (int mi = 0; mi < 2; mi++)
                #pragma unroll
                for (int ni = 0; ni < 8; ni++)
                    mma_tf32(acc[mi][ni], af[mi], bf[ni]);
        }

        if (t + 1 < T) store_smem((t + 1) & 1);
        __syncthreads();
    }

    // epilogue
    #pragma unroll
    for (int mi = 0; mi < 2; mi++) {
        int r0 = rowBase + wm * 32 + mi * 16 + qr;
        #pragma unroll
        for (int ni = 0; ni < 8; ni++) {
            int cc = colBase + wn * 64 + ni * 8 + qt * 2;
            float b0 = bias[cc], b1 = bias[cc + 1];
            float v0 = acc[mi][ni][0] + b0;
            float v1 = acc[mi][ni][1] + b1;
            float v2 = acc[mi][ni][2] + b0;
            float v3 = acc[mi][ni][3] + b1;
            if (RES) {
                v0 += res[(size_t)r0 * N + cc];
                v1 += res[(size_t)r0 * N + cc + 1];
                v2 += res[(size_t)(r0 + 8) * N + cc];
                v3 += res[(size_t)(r0 + 8) * N + cc + 1];
            }
            if (ACT == 1) { v0 = gelu_f(v0); v1 = gelu_f(v1); v2 = gelu_f(v2); v3 = gelu_f(v3); }
            *(float2*)(C + (size_t)r0 * N + cc)       = make_float2(v0, v1);
            *(float2*)(C + (size_t)(r0 + 8) * N + cc) = make_float2(v2, v3);
        }
    }
}

// ---------------- Fused attention (scalar; next-round target) ----------------
__global__ __launch_bounds__(256) void attn_kernel(const float* __restrict__ Q,
                                                   const float* __restrict__ K,
                                                   const float* __restrict__ V,
                                                   const int* __restrict__ mask,
                                                   float* __restrict__ O)
{
    __shared__ float Qs[64][65];
    __shared__ float Ks[32][65];
    __shared__ float Vs[32][65];
    __shared__ float Ps[64][33];
    __shared__ float Red[64][17];

    int qt = blockIdx.x, h = blockIdx.y, b = blockIdx.z;
    int tid = threadIdx.x;
    int ty = tid >> 4, tx = tid & 15;
    int q0 = qt * 64;
    int r0 = ty * 4;
    int c0 = tx * 2;
    int d0 = tx * 4;

    for (int i = tid; i < 64 * 64; i += 256) {
        int r = i >> 6, d = i & 63;
        Qs[r][d] = Q[(size_t)(b*Sz + q0 + r) * Ez + h*HDz + d] * 0.125f;
    }

    float acc[4][4];
    #pragma unroll
    for (int i = 0; i < 4; i++)
        #pragma unroll
        for (int j = 0; j < 4; j++) acc[i][j] = 0.0f;
    float rs[4] = {0.f, 0.f, 0.f, 0.f};

    for (int k0 = 0; k0 < Sz; k0 += 32) {
        __syncthreads();
        for (int i = tid; i < 32 * 64; i += 256) {
            int r = i >> 6, d = i & 63;
            size_t gi = (size_t)(b*Sz + k0 + r) * Ez + h*HDz + d;
            Ks[r][d] = K[gi];
            Vs[r][d] = V[gi];
        }
        __syncthreads();

        float sv[4][2];
        #pragma unroll
        for (int i = 0; i < 4; i++) { sv[i][0] = 0.f; sv[i][1] = 0.f; }
        #pragma unroll 8
        for (int d = 0; d < 64; d++) {
            float qa0 = Qs[r0+0][d], qa1 = Qs[r0+1][d], qa2 = Qs[r0+2][d], qa3 = Qs[r0+3][d];
            float kb0 = Ks[c0+0][d], kb1 = Ks[c0+1][d];
            sv[0][0] += qa0*kb0; sv[0][1] += qa0*kb1;
            sv[1][0] += qa1*kb0; sv[1][1] += qa1*kb1;
            sv[2][0] += qa2*kb0; sv[2][1] += qa2*kb1;
            sv[3][0] += qa3*kb0; sv[3][1] += qa3*kb1;
        }
        #pragma unroll
        for (int i = 0; i < 4; i++) {
            int gq = q0 + r0 + i;
            const int* mrow = mask + (size_t)(b*Sz + gq) * Sz + k0;
            #pragma unroll
            for (int j = 0; j < 2; j++) {
                int m = mrow[c0 + j];
                float s = m ? sv[i][j] : -0.01f;
                float p = __expf(s);
                rs[i] += p;
                Ps[r0+i][c0+j] = p;
            }
        }
        __syncthreads();

        #pragma unroll 4
        for (int kk = 0; kk < 32; kk++) {
            float p0 = Ps[r0+0][kk], p1 = Ps[r0+1][kk], p2 = Ps[r0+2][kk], p3 = Ps[r0+3][kk];
            float v0 = Vs[kk][d0+0], v1 = Vs[kk][d0+1], v2 = Vs[kk][d0+2], v3 = Vs[kk][d0+3];
            acc[0][0]+=p0*v0; acc[0][1]+=p0*v1; acc[0][2]+=p0*v2; acc[0][3]+=p0*v3;
            acc[1][0]+=p1*v0; acc[1][1]+=p1*v1; acc[1][2]+=p1*v2; acc[1][3]+=p1*v3;
            acc[2][0]+=p2*v0; acc[2][1]+=p2*v1; acc[2][2]+=p2*v2; acc[2][3]+=p2*v3;
            acc[3][0]+=p3*v0; acc[3][1]+=p3*v1; acc[3][2]+=p3*v2; acc[3][3]+=p3*v3;
        }
    }

    __syncthreads();
    #pragma unroll
    for (int i = 0; i < 4; i++) Red[r0+i][tx] = rs[i];
    __syncthreads();
    float l[4];
    #pragma unroll
    for (int i = 0; i < 4; i++) {
        float t = 0.f;
        #pragma unroll
        for (int u = 0; u < 16; u++) t += Red[r0+i][u];
        l[i] = t;
    }

    #pragma unroll
    for (int i = 0; i < 4; i++) {
        float inv = 1.0f / l[i];
        #pragma unroll
        for (int j = 0; j < 4; j++) {
            O[(size_t)(b*Sz + q0 + r0 + i) * Ez + h*HDz + d0 + j] = acc[i][j] * inv;
        }
    }
}

// ---------------- launch ----------------
extern "C" void kernel_launch(void* const* d_in, const int* in_sizes, int n_in,
                              void* d_out, int out_size)
{
    const float* x   = (const float*)d_in[0];
    const int*   msk = (const int*)  d_in[1];
    const float* Wq  = (const float*)d_in[2];
    const float* bq  = (const float*)d_in[3];
    const float* Wk  = (const float*)d_in[4];
    const float* bk  = (const float*)d_in[5];
    const float* Wv  = (const float*)d_in[6];
    const float* bv  = (const float*)d_in[7];
    const float* Wo  = (const float*)d_in[8];
    const float* bo  = (const float*)d_in[9];
    const float* W1  = (const float*)d_in[10];
    const float* b1  = (const float*)d_in[11];
    const float* W2  = (const float*)d_in[12];
    const float* b2  = (const float*)d_in[13];
    const float* g1  = (const float*)d_in[14];
    const float* be1 = (const float*)d_in[15];
    const float* g2  = (const float*)d_in[16];
    const float* be2 = (const float*)d_in[17];
    float* out = (float*)d_out;

    float *nx, *q, *k, *v, *o, *x1, *nx2, *h1;
    cudaGetSymbolAddress((void**)&nx,  g_nx);
    cudaGetSymbolAddress((void**)&q,   g_q);
    cudaGetSymbolAddress((void**)&k,   g_k);
    cudaGetSymbolAddress((void**)&v,   g_v);
    cudaGetSymbolAddress((void**)&o,   g_o);
    cudaGetSymbolAddress((void**)&x1,  g_x1);
    cudaGetSymbolAddress((void**)&nx2, g_nx2);
    cudaGetSymbolAddress((void**)&h1,  g_h1);

    static bool attr_done = false;
    if (!attr_done) {
        cudaFuncSetAttribute(gemm_tf32<0,false>, cudaFuncAttributeMaxDynamicSharedMemorySize, GEMM_SMEM);
        cudaFuncSetAttribute(gemm_tf32<0,true>,  cudaFuncAttributeMaxDynamicSharedMemorySize, GEMM_SMEM);
        cudaFuncSetAttribute(gemm_tf32<1,false>, cudaFuncAttributeMaxDynamicSharedMemorySize, GEMM_SMEM);
        attr_done = true;
    }

    dim3 gE(Ez/BN,   Mz/BM);   // N=1024
    dim3 gF(DFFz/BN, Mz/BM);   // N=4096

    // 1) LN1
    ln_kernel<<<Mz, 256>>>(x, g1, be1, nx);
    // 2-4) Q, K, V projections
    gemm_tf32<0,false><<<gE, 256, GEMM_SMEM>>>(nx, Wq, bq, nullptr, q, Mz, Ez, Ez);
    gemm_tf32<0,false><<<gE, 256, GEMM_SMEM>>>(nx, Wk, bk, nullptr, k, Mz, Ez, Ez);
    gemm_tf32<0,false><<<gE, 256, GEMM_SMEM>>>(nx, Wv, bv, nullptr, v, Mz, Ez, Ez);
    // 5) attention
    attn_kernel<<<dim3(Sz/64, Hz, Bz), 256>>>(q, k, v, msk, o);
    // 6) output projection + residual
    gemm_tf32<0,true><<<gE, 256, GEMM_SMEM>>>(o, Wo, bo, x, x1, Mz, Ez, Ez);
    // 7) LN2
    ln_kernel<<<Mz, 256>>>(x1, g2, be2, nx2);
    // 8) FFN up + GELU
    gemm_tf32<1,false><<<gF, 256, GEMM_SMEM>>>(nx2, W1, b1, nullptr, h1, Mz, DFFz, Ez);
    // 9) FFN down + residual -> out
    gemm_tf32<0,true><<<gE, 256, GEMM_SMEM>>>(h1, W2, b2, x1, out, Mz, Ez, DFFz);
}

// round 5
// speedup vs baseline: 3.3881x; 1.6088x over previous
#include <cuda_runtime.h>
#include <cuda_bf16.h>
#include <math.h>

// Shapes (fixed)
#define Bz 4
#define Sz 1024
#define Ez 1024
#define Hz 16
#define HDz 64
#define DFFz 4096
#define Mz (Bz*Sz)   // 4096 rows of activations

// ---------------- scratch (device globals; no allocations) ----------------
__device__ float g_nx [Mz*Ez];
__device__ float g_q  [Mz*Ez];
__device__ float g_k  [Mz*Ez];
__device__ float g_v  [Mz*Ez];
__device__ float g_o  [Mz*Ez];
__device__ float g_x1 [Mz*Ez];
__device__ float g_nx2[Mz*Ez];
__device__ float g_h1 [(size_t)Mz*DFFz];

// ---------------- helpers ----------------
__device__ __forceinline__ float gelu_f(float x) {
    const float c = 0.7978845608028654f; // sqrt(2/pi)
    float u = c * (x + 0.044715f * x * x * x);
    return 0.5f * x * (1.0f + tanhf(u));
}

__device__ __forceinline__ void mma_tf32(float* c, const unsigned* a, const unsigned* b) {
    asm volatile(
        "mma.sync.aligned.m16n8k8.row.col.f32.tf32.tf32.f32 "
        "{%0,%1,%2,%3}, {%4,%5,%6,%7}, {%8,%9}, {%0,%1,%2,%3};\n"
        : "+f"(c[0]), "+f"(c[1]), "+f"(c[2]), "+f"(c[3])
        : "r"(a[0]), "r"(a[1]), "r"(a[2]), "r"(a[3]),
          "r"(b[0]), "r"(b[1]));
}

__device__ __forceinline__ void cp_async16(void* sdst, const void* gsrc) {
    unsigned s = (unsigned)__cvta_generic_to_shared(sdst);
    asm volatile("cp.async.cg.shared.global [%0], [%1], 16;\n" :: "r"(s), "l"(gsrc));
}
__device__ __forceinline__ void cp_commit() {
    asm volatile("cp.async.commit_group;\n" ::);
}
template<int N>
__device__ __forceinline__ void cp_wait() {
    asm volatile("cp.async.wait_group %0;\n" :: "n"(N));
}

// ---------------- LayerNorm (ddof=1, eps added to std) ----------------
__global__ __launch_bounds__(256) void ln_kernel(const float* __restrict__ x,
                                                 const float* __restrict__ g,
                                                 const float* __restrict__ be,
                                                 float* __restrict__ y)
{
    __shared__ float red[32];
    int row = blockIdx.x;
    int tid = threadIdx.x;
    const float4* xr = (const float4*)(x + (size_t)row * Ez);
    float4 v = xr[tid];

    float s = v.x + v.y + v.z + v.w;
    #pragma unroll
    for (int o = 16; o > 0; o >>= 1) s += __shfl_xor_sync(0xffffffffu, s, o);
    if ((tid & 31) == 0) red[tid >> 5] = s;
    __syncthreads();
    float t = (tid < 8) ? red[tid] : 0.0f;
    if (tid < 32) {
        #pragma unroll
        for (int o = 4; o > 0; o >>= 1) t += __shfl_xor_sync(0xffffffffu, t, o);
        if (tid == 0) red[0] = t;
    }
    __syncthreads();
    float mean = red[0] * (1.0f / Ez);
    __syncthreads();

    float dx = v.x - mean, dy = v.y - mean, dz = v.z - mean, dw = v.w - mean;
    float sq = dx*dx + dy*dy + dz*dz + dw*dw;
    #pragma unroll
    for (int o = 16; o > 0; o >>= 1) sq += __shfl_xor_sync(0xffffffffu, sq, o);
    if ((tid & 31) == 0) red[tid >> 5] = sq;
    __syncthreads();
    float t2 = (tid < 8) ? red[tid] : 0.0f;
    if (tid < 32) {
        #pragma unroll
        for (int o = 4; o > 0; o >>= 1) t2 += __shfl_xor_sync(0xffffffffu, t2, o);
        if (tid == 0) red[0] = t2;
    }
    __syncthreads();
    float var = red[0] * (1.0f / (Ez - 1));
    float inv = 1.0f / (sqrtf(var) + 1e-8f);

    float4 gg = ((const float4*)g)[tid];
    float4 bb = ((const float4*)be)[tid];
    float4 o4;
    o4.x = gg.x * dx * inv + bb.x;
    o4.y = gg.y * dy * inv + bb.y;
    o4.z = gg.z * dz * inv + bb.z;
    o4.w = gg.w * dw * inv + bb.w;
    ((float4*)(y + (size_t)row * Ez))[tid] = o4;
}

// ---------------- TF32 tensor-core GEMM, cp.async 4-stage pipeline ----------------
// C[M,N] = A[M,K] * B[N,K]^T + bias[N] (+res) (+gelu)
#define BM 128
#define BN 128
#define BK 32
#define KST 36      // stride pad: conflict-free fragment loads (36 mod 32 == 4)
#define STAGES 4

#define GEMM_SMEM (STAGES*(BM+BN)*KST*4)

template<int ACT, bool RES>
__global__ __launch_bounds__(256) void gemm_tf32(const float* __restrict__ A,
                                                 const float* __restrict__ Bm,
                                                 const float* __restrict__ bias,
                                                 const float* __restrict__ res,
                                                 float* __restrict__ C,
                                                 int M, int N, int K)
{
    extern __shared__ float smem[];
    float* As = smem;                           // [STAGES][BM][KST]
    float* Bs = smem + STAGES * BM * KST;       // [STAGES][BN][KST]

    const int tid  = threadIdx.x;
    const int warp = tid >> 5, lane = tid & 31;
    const int wm = warp >> 1, wn = warp & 1;    // 4 x 2 warp grid
    const int qr = lane >> 2, qt = lane & 3;
    const int rowBase = blockIdx.y * BM;
    const int colBase = blockIdx.x * BN;

    float acc[2][8][4];
    #pragma unroll
    for (int mi = 0; mi < 2; mi++)
        #pragma unroll
        for (int ni = 0; ni < 8; ni++)
            #pragma unroll
            for (int r = 0; r < 4; r++) acc[mi][ni][r] = 0.0f;

    auto prefetch = [&](int k0, int buf) {
        float* as = As + buf * BM * KST;
        float* bs = Bs + buf * BN * KST;
        #pragma unroll
        for (int l = 0; l < 4; l++) {
            int idx = l * 256 + tid;
            int r = idx >> 3, c = idx & 7;
            cp_async16(as + r * KST + c * 4, A  + (size_t)(rowBase + r) * K + k0 + c * 4);
            cp_async16(bs + r * KST + c * 4, Bm + (size_t)(colBase + r) * K + k0 + c * 4);
        }
    };

    const int T = K / BK;
    #pragma unroll
    for (int s = 0; s < STAGES - 1; s++) { prefetch(s * BK, s); cp_commit(); }

    for (int t = 0; t < T; t++) {
        cp_wait<STAGES - 2>();
        __syncthreads();
        if (t + STAGES - 1 < T) prefetch((t + STAGES - 1) * BK, (t + STAGES - 1) % STAGES);
        cp_commit();   // always commit (keeps group-indexing aligned at the tail)

        const unsigned* as = (const unsigned*)(As + (t % STAGES) * BM * KST) + (wm * 32) * KST;
        const unsigned* bs = (const unsigned*)(Bs + (t % STAGES) * BN * KST) + (wn * 64) * KST;

        #pragma unroll
        for (int kk = 0; kk < BK; kk += 8) {
            unsigned af[2][4], bf[8][2];
            #pragma unroll
            for (int mi = 0; mi < 2; mi++) {
                int base = (mi * 16 + qr) * KST + kk + qt;
                af[mi][0] = as[base];
                af[mi][1] = as[base + 8 * KST];
                af[mi][2] = as[base + 4];
                af[mi][3] = as[base + 8 * KST + 4];
            }
            #pragma unroll
            for (int ni = 0; ni < 8; ni++) {
                int base = (ni * 8 + qr) * KST + kk + qt;
                bf[ni][0] = bs[base];
                bf[ni][1] = bs[base + 4];
            }
            #pragma unroll
            for (int mi = 0; mi < 2; mi++)
                #pragma unroll
                for (int ni = 0; ni < 8; ni++)
                    mma_tf32(acc[mi][ni], af[mi], bf[ni]);
        }
    }

    // epilogue
    #pragma unroll
    for (int mi = 0; mi < 2; mi++) {
        int r0 = rowBase + wm * 32 + mi * 16 + qr;
        #pragma unroll
        for (int ni = 0; ni < 8; ni++) {
            int cc = colBase + wn * 64 + ni * 8 + qt * 2;
            float b0 = bias[cc], b1 = bias[cc + 1];
            float v0 = acc[mi][ni][0] + b0;
            float v1 = acc[mi][ni][1] + b1;
            float v2 = acc[mi][ni][2] + b0;
            float v3 = acc[mi][ni][3] + b1;
            if (RES) {
                v0 += res[(size_t)r0 * N + cc];
                v1 += res[(size_t)r0 * N + cc + 1];
                v2 += res[(size_t)(r0 + 8) * N + cc];
                v3 += res[(size_t)(r0 + 8) * N + cc + 1];
            }
            if (ACT == 1) { v0 = gelu_f(v0); v1 = gelu_f(v1); v2 = gelu_f(v2); v3 = gelu_f(v3); }
            *(float2*)(C + (size_t)r0 * N + cc)       = make_float2(v0, v1);
            *(float2*)(C + (size_t)(r0 + 8) * N + cc) = make_float2(v2, v3);
        }
    }
}

// ---------------- Tensor-core fused attention ----------------
// grid (S/64, H, B), 256 threads (8 warps: 4 row-groups x 2 col-groups).
// Per 64-chunk: S = Q*K^T (mma), P = exp(mask? S : -0.01) -> smem, O += P*V (mma).
// No online softmax: masked score is finite (-0.01); divide by row-sum at the end.
// Smem strides: 68 (==4 mod 32) makes A/B frag loads at (qr*st + qt) conflict-free;
// 72 (==8 mod 32) makes V B-frag loads at (qt*st + qr) conflict-free (no transpose).
#define QS_ST 68
#define VS_ST 72
#define ATTN_SMEM ((64*68 /*Q*/ + 2*64*68 /*K*/ + 2*64*72 /*V*/ + 64*68 /*P*/ + 2*64*68 /*mask*/) * 4)

__global__ __launch_bounds__(256) void attn_mma(const float* __restrict__ Q,
                                                const float* __restrict__ K,
                                                const float* __restrict__ V,
                                                const int* __restrict__ mask,
                                                float* __restrict__ O)
{
    extern __shared__ float sm[];
    float* Qs = sm;                      // [64][68]
    float* Ks = sm + 4352;               // [2][64][68]
    float* Vs = sm + 13056;              // [2][64][72]
    float* Ps = sm + 22272;              // [64][68]
    int*   Ms = (int*)(sm + 26624);      // [2][64][68]

    const int qt_ = blockIdx.x, h = blockIdx.y, b = blockIdx.z;
    const int q0 = qt_ * 64;
    const int tid = threadIdx.x;
    const int warp = tid >> 5, lane = tid & 31;
    const int wm = warp >> 1, wn = warp & 1;
    const int qr = lane >> 2, qt = lane & 3;

    // load Q tile (scaled by 1/sqrt(HD))
    #pragma unroll
    for (int l = 0; l < 4; l++) {
        int i = l * 256 + tid;          // 0..1023 float4s
        int r = i >> 4, c = (i & 15) * 4;
        float4 v = *(const float4*)(Q + (size_t)(b*Sz + q0 + r) * Ez + h*HDz + c);
        float* d = Qs + r * QS_ST + c;
        d[0] = v.x * 0.125f; d[1] = v.y * 0.125f;
        d[2] = v.z * 0.125f; d[3] = v.w * 0.125f;
    }

    auto prefetch = [&](int t, int buf) {
        int k0 = t * 64;
        #pragma unroll
        for (int l = 0; l < 4; l++) {
            int idx = l * 256 + tid;
            int r = idx >> 4, c = (idx & 15) * 4;
            cp_async16(Ks + buf*4352 + r*QS_ST + c, K + (size_t)(b*Sz + k0 + r) * Ez + h*HDz + c);
            cp_async16(Vs + buf*4608 + r*VS_ST + c, V + (size_t)(b*Sz + k0 + r) * Ez + h*HDz + c);
            cp_async16(Ms + buf*4352 + r*QS_ST + c, mask + (size_t)(b*Sz + q0 + r) * Sz + k0 + c);
        }
    };

    prefetch(0, 0); cp_commit();

    float acc[4][4];
    #pragma unroll
    for (int j = 0; j < 4; j++)
        #pragma unroll
        for (int r = 0; r < 4; r++) acc[j][r] = 0.0f;
    float rs0 = 0.f, rs1 = 0.f;
    const float EM = 0.99004983374916805f;   // exp(-0.01)

    for (int t = 0; t < Sz/64; t++) {
        int buf = t & 1;
        cp_wait<0>();
        __syncthreads();
        if (t + 1 < Sz/64) { prefetch(t + 1, buf ^ 1); cp_commit(); }

        // ---- scores: warp (wm,wn) -> rows wm*16.., kcols wn*32 + j*8 ----
        const unsigned* qsb = (const unsigned*)(Qs + (wm*16) * QS_ST);
        const unsigned* ksb = (const unsigned*)(Ks + buf*4352 + (wn*32) * QS_ST);
        float sc[4][4];
        #pragma unroll
        for (int j = 0; j < 4; j++)
            #pragma unroll
            for (int r = 0; r < 4; r++) sc[j][r] = 0.0f;

        #pragma unroll
        for (int kk = 0; kk < 64; kk += 8) {
            unsigned af[4];
            af[0] = qsb[qr * QS_ST + kk + qt];
            af[1] = qsb[(qr + 8) * QS_ST + kk + qt];
            af[2] = qsb[qr * QS_ST + kk + qt + 4];
            af[3] = qsb[(qr + 8) * QS_ST + kk + qt + 4];
            #pragma unroll
            for (int j = 0; j < 4; j++) {
                unsigned bf[2];
                bf[0] = ksb[(j*8 + qr) * QS_ST + kk + qt];
                bf[1] = ksb[(j*8 + qr) * QS_ST + kk + qt + 4];
                mma_tf32(sc[j], af, bf);
            }
        }

        // ---- mask + exp -> P smem, accumulate row sums ----
        const int mrow0 = (wm*16 + qr) * QS_ST;
        const int mrow1 = (wm*16 + qr + 8) * QS_ST;
        const int* Mb = Ms + buf * 4352;
        #pragma unroll
        for (int j = 0; j < 4; j++) {
            int cc = wn*32 + j*8 + 2*qt;
            int2 m0 = *(const int2*)(Mb + mrow0 + cc);
            int2 m1 = *(const int2*)(Mb + mrow1 + cc);
            float p00 = m0.x ? __expf(sc[j][0]) : EM;
            float p01 = m0.y ? __expf(sc[j][1]) : EM;
            float p10 = m1.x ? __expf(sc[j][2]) : EM;
            float p11 = m1.y ? __expf(sc[j][3]) : EM;
            rs0 += p00 + p01;
            rs1 += p10 + p11;
            *(float2*)(Ps + mrow0 + cc) = make_float2(p00, p01);
            *(float2*)(Ps + mrow1 + cc) = make_float2(p10, p11);
        }
        __syncthreads();

        // ---- O += P * V : rows wm*16.., d-cols wn*32 + j*8 ----
        const unsigned* psb = (const unsigned*)(Ps + (wm*16) * QS_ST);
        const unsigned* vsb = (const unsigned*)(Vs + buf*4608 + wn*32);
        #pragma unroll
        for (int kk = 0; kk < 64; kk += 8) {
            unsigned af[4];
            af[0] = psb[qr * QS_ST + kk + qt];
            af[1] = psb[(qr + 8) * QS_ST + kk + qt];
            af[2] = psb[qr * QS_ST + kk + qt + 4];
            af[3] = psb[(qr + 8) * QS_ST + kk + qt + 4];
            #pragma unroll
            for (int j = 0; j < 4; j++) {
                unsigned bf[2];
                bf[0] = vsb[(kk + qt) * VS_ST + j*8 + qr];
                bf[1] = vsb[(kk + qt + 4) * VS_ST + j*8 + qr];
                mma_tf32(acc[j], af, bf);
            }
        }
        __syncthreads();   // PV reads done before next iter's P writes / V prefetch use
    }

    // ---- row sums: reduce over qt lanes, then across wn via smem ----
    rs0 += __shfl_xor_sync(0xffffffffu, rs0, 1);
    rs0 += __shfl_xor_sync(0xffffffffu, rs0, 2);
    rs1 += __shfl_xor_sync(0xffffffffu, rs1, 1);
    rs1 += __shfl_xor_sync(0xffffffffu, rs1, 2);
    if (qt == 0) {
        Ps[(wm*16 + qr) * 2 + wn]     = rs0;
        Ps[(wm*16 + qr + 8) * 2 + wn] = rs1;
    }
    __syncthreads();
    float inv0 = 1.0f / (Ps[(wm*16 + qr) * 2 + 0]     + Ps[(wm*16 + qr) * 2 + 1]);
    float inv1 = 1.0f / (Ps[(wm*16 + qr + 8) * 2 + 0] + Ps[(wm*16 + qr + 8) * 2 + 1]);

    // ---- write O ----
    const size_t row0 = (size_t)(b*Sz + q0 + wm*16 + qr);
    #pragma unroll
    for (int j = 0; j < 4; j++) {
        int cc = h*HDz + wn*32 + j*8 + 2*qt;
        *(float2*)(O + row0 * Ez + cc)       = make_float2(acc[j][0] * inv0, acc[j][1] * inv0);
        *(float2*)(O + (row0 + 8) * Ez + cc) = make_float2(acc[j][2] * inv1, acc[j][3] * inv1);
    }
}

// ---------------- launch ----------------
extern "C" void kernel_launch(void* const* d_in, const int* in_sizes, int n_in,
                              void* d_out, int out_size)
{
    const float* x   = (const float*)d_in[0];
    const int*   msk = (const int*)  d_in[1];
    const float* Wq  = (const float*)d_in[2];
    const float* bq  = (const float*)d_in[3];
    const float* Wk  = (const float*)d_in[4];
    const float* bk  = (const float*)d_in[5];
    const float* Wv  = (const float*)d_in[6];
    const float* bv  = (const float*)d_in[7];
    const float* Wo  = (const float*)d_in[8];
    const float* bo  = (const float*)d_in[9];
    const float* W1  = (const float*)d_in[10];
    const float* b1  = (const float*)d_in[11];
    const float* W2  = (const float*)d_in[12];
    const float* b2  = (const float*)d_in[13];
    const float* g1  = (const float*)d_in[14];
    const float* be1 = (const float*)d_in[15];
    const float* g2  = (const float*)d_in[16];
    const float* be2 = (const float*)d_in[17];
    float* out = (float*)d_out;

    float *nx, *q, *k, *v, *o, *x1, *nx2, *h1;
    cudaGetSymbolAddress((void**)&nx,  g_nx);
    cudaGetSymbolAddress((void**)&q,   g_q);
    cudaGetSymbolAddress((void**)&k,   g_k);
    cudaGetSymbolAddress((void**)&v,   g_v);
    cudaGetSymbolAddress((void**)&o,   g_o);
    cudaGetSymbolAddress((void**)&x1,  g_x1);
    cudaGetSymbolAddress((void**)&nx2, g_nx2);
    cudaGetSymbolAddress((void**)&h1,  g_h1);

    static bool attr_done = false;
    if (!attr_done) {
        cudaFuncSetAttribute(gemm_tf32<0,false>, cudaFuncAttributeMaxDynamicSharedMemorySize, GEMM_SMEM);
        cudaFuncSetAttribute(gemm_tf32<0,true>,  cudaFuncAttributeMaxDynamicSharedMemorySize, GEMM_SMEM);
        cudaFuncSetAttribute(gemm_tf32<1,false>, cudaFuncAttributeMaxDynamicSharedMemorySize, GEMM_SMEM);
        cudaFuncSetAttribute(attn_mma,           cudaFuncAttributeMaxDynamicSharedMemorySize, ATTN_SMEM);
        attr_done = true;
    }

    dim3 gE(Ez/BN,   Mz/BM);   // N=1024
    dim3 gF(DFFz/BN, Mz/BM);   // N=4096

    // 1) LN1
    ln_kernel<<<Mz, 256>>>(x, g1, be1, nx);
    // 2-4) Q, K, V projections
    gemm_tf32<0,false><<<gE, 256, GEMM_SMEM>>>(nx, Wq, bq, nullptr, q, Mz, Ez, Ez);
    gemm_tf32<0,false><<<gE, 256, GEMM_SMEM>>>(nx, Wk, bk, nullptr, k, Mz, Ez, Ez);
    gemm_tf32<0,false><<<gE, 256, GEMM_SMEM>>>(nx, Wv, bv, nullptr, v, Mz, Ez, Ez);
    // 5) attention (tensor cores)
    attn_mma<<<dim3(Sz/64, Hz, Bz), 256, ATTN_SMEM>>>(q, k, v, msk, o);
    // 6) output projection + residual
    gemm_tf32<0,true><<<gE, 256, GEMM_SMEM>>>(o, Wo, bo, x, x1, Mz, Ez, Ez);
    // 7) LN2
    ln_kernel<<<Mz, 256>>>(x1, g2, be2, nx2);
    // 8) FFN up + GELU
    gemm_tf32<1,false><<<gF, 256, GEMM_SMEM>>>(nx2, W1, b1, nullptr, h1, Mz, DFFz, Ez);
    // 9) FFN down + residual -> out
    gemm_tf32<0,true><<<gE, 256, GEMM_SMEM>>>(h1, W2, b2, x1, out, Mz, Ez, DFFz);
}

// round 7
// speedup vs baseline: 3.4284x; 1.0119x over previous
#include <cuda_runtime.h>
#include <cuda_bf16.h>
#include <math.h>

// Shapes (fixed)
#define Bz 4
#define Sz 1024
#define Ez 1024
#define Hz 16
#define HDz 64
#define DFFz 4096
#define Mz (Bz*Sz)   // 4096 rows of activations

// ---------------- scratch (device globals; no allocations) ----------------
__device__ float g_nx [Mz*Ez];
__device__ float g_q  [Mz*Ez];
__device__ float g_k  [Mz*Ez];
__device__ float g_v  [Mz*Ez];
__device__ float g_o  [Mz*Ez];
__device__ float g_x1 [Mz*Ez];
__device__ float g_nx2[Mz*Ez];
__device__ float g_h1 [(size_t)Mz*DFFz];
// tf32-rounded weights
__device__ float g_wq [Ez*Ez];
__device__ float g_wk [Ez*Ez];
__device__ float g_wv [Ez*Ez];
__device__ float g_wo [Ez*Ez];
__device__ float g_w1 [(size_t)DFFz*Ez];
__device__ float g_w2 [(size_t)Ez*DFFz];

// ---------------- helpers ----------------
__device__ __forceinline__ float gelu_f(float x) {
    const float c = 0.7978845608028654f; // sqrt(2/pi)
    float u = c * (x + 0.044715f * x * x * x);
    return 0.5f * x * (1.0f + tanhf(u));
}

// round fp32 to tf32 (RNA), keep as fp32 storage (low 13 bits zero)
__device__ __forceinline__ float rnd_tf32(float x) {
    unsigned r;
    asm("cvt.rna.tf32.f32 %0, %1;" : "=r"(r) : "f"(x));
    return __uint_as_float(r);
}

__device__ __forceinline__ void mma_tf32(float* c, const unsigned* a, const unsigned* b) {
    asm volatile(
        "mma.sync.aligned.m16n8k8.row.col.f32.tf32.tf32.f32 "
        "{%0,%1,%2,%3}, {%4,%5,%6,%7}, {%8,%9}, {%0,%1,%2,%3};\n"
        : "+f"(c[0]), "+f"(c[1]), "+f"(c[2]), "+f"(c[3])
        : "r"(a[0]), "r"(a[1]), "r"(a[2]), "r"(a[3]),
          "r"(b[0]), "r"(b[1]));
}

__device__ __forceinline__ void cp_async16(void* sdst, const void* gsrc) {
    unsigned s = (unsigned)__cvta_generic_to_shared(sdst);
    asm volatile("cp.async.cg.shared.global [%0], [%1], 16;\n" :: "r"(s), "l"(gsrc));
}
__device__ __forceinline__ void cp_commit() {
    asm volatile("cp.async.commit_group;\n" ::);
}
template<int N>
__device__ __forceinline__ void cp_wait() {
    asm volatile("cp.async.wait_group %0;\n" :: "n"(N));
}

// ---------------- elementwise tf32-RNA rounding (for weights) ----------------
__global__ __launch_bounds__(256) void round_kernel(const float* __restrict__ in,
                                                    float* __restrict__ out, int n4)
{
    int i = blockIdx.x * 256 + threadIdx.x;
    if (i < n4) {
        float4 v = ((const float4*)in)[i];
        v.x = rnd_tf32(v.x); v.y = rnd_tf32(v.y);
        v.z = rnd_tf32(v.z); v.w = rnd_tf32(v.w);
        ((float4*)out)[i] = v;
    }
}

// ---------------- LayerNorm (ddof=1, eps added to std); output tf32-rounded ----------------
__global__ __launch_bounds__(256) void ln_kernel(const float* __restrict__ x,
                                                 const float* __restrict__ g,
                                                 const float* __restrict__ be,
                                                 float* __restrict__ y)
{
    __shared__ float red[32];
    int row = blockIdx.x;
    int tid = threadIdx.x;
    const float4* xr = (const float4*)(x + (size_t)row * Ez);
    float4 v = xr[tid];

    float s = v.x + v.y + v.z + v.w;
    #pragma unroll
    for (int o = 16; o > 0; o >>= 1) s += __shfl_xor_sync(0xffffffffu, s, o);
    if ((tid & 31) == 0) red[tid >> 5] = s;
    __syncthreads();
    float t = (tid < 8) ? red[tid] : 0.0f;
    if (tid < 32) {
        #pragma unroll
        for (int o = 4; o > 0; o >>= 1) t += __shfl_xor_sync(0xffffffffu, t, o);
        if (tid == 0) red[0] = t;
    }
    __syncthreads();
    float mean = red[0] * (1.0f / Ez);
    __syncthreads();

    float dx = v.x - mean, dy = v.y - mean, dz = v.z - mean, dw = v.w - mean;
    float sq = dx*dx + dy*dy + dz*dz + dw*dw;
    #pragma unroll
    for (int o = 16; o > 0; o >>= 1) sq += __shfl_xor_sync(0xffffffffu, sq, o);
    if ((tid & 31) == 0) red[tid >> 5] = sq;
    __syncthreads();
    float t2 = (tid < 8) ? red[tid] : 0.0f;
    if (tid < 32) {
        #pragma unroll
        for (int o = 4; o > 0; o >>= 1) t2 += __shfl_xor_sync(0xffffffffu, t2, o);
        if (tid == 0) red[0] = t2;
    }
    __syncthreads();
    float var = red[0] * (1.0f / (Ez - 1));
    float inv = 1.0f / (sqrtf(var) + 1e-8f);

    float4 gg = ((const float4*)g)[tid];
    float4 bb = ((const float4*)be)[tid];
    float4 o4;
    o4.x = rnd_tf32(gg.x * dx * inv + bb.x);
    o4.y = rnd_tf32(gg.y * dy * inv + bb.y);
    o4.z = rnd_tf32(gg.z * dz * inv + bb.z);
    o4.w = rnd_tf32(gg.w * dw * inv + bb.w);
    ((float4*)(y + (size_t)row * Ez))[tid] = o4;
}

// ---------------- TF32 tensor-core GEMM, cp.async 3-stage pipeline ----------------
// C[M,N] = A[M,K] * B[N,K]^T + bias[N] (+res) (+gelu) (+tf32-round stores)
// 128x256x32 CTA tile, 8 warps (2x4), 64x64 warp tile.
#define BM 128
#define BN 256
#define BK 32
#define KST 36      // stride pad: conflict-free fragment loads (36 mod 32 == 4)
#define STAGES 3

#define GEMM_SMEM (STAGES*(BM+BN)*KST*4)

template<int ACT, bool RES, bool RND>
__global__ __launch_bounds__(256) void gemm_tf32(const float* __restrict__ A,
                                                 const float* __restrict__ Bm,
                                                 const float* __restrict__ bias,
                                                 const float* __restrict__ res,
                                                 float* __restrict__ C,
                                                 int M, int N, int K)
{
    extern __shared__ float smem[];
    float* As = smem;                           // [STAGES][BM][KST]
    float* Bs = smem + STAGES * BM * KST;       // [STAGES][BN][KST]

    const int tid  = threadIdx.x;
    const int warp = tid >> 5, lane = tid & 31;
    const int wm = warp >> 2, wn = warp & 3;    // 2 x 4 warp grid, 64x64 warp tile
    const int qr = lane >> 2, qt = lane & 3;
    const int rowBase = blockIdx.y * BM;
    const int colBase = blockIdx.x * BN;

    float acc[4][8][4];
    #pragma unroll
    for (int mi = 0; mi < 4; mi++)
        #pragma unroll
        for (int ni = 0; ni < 8; ni++)
            #pragma unroll
            for (int r = 0; r < 4; r++) acc[mi][ni][r] = 0.0f;

    auto prefetch = [&](int k0, int buf) {
        float* as = As + buf * BM * KST;
        float* bs = Bs + buf * BN * KST;
        #pragma unroll
        for (int l = 0; l < 4; l++) {          // A: 128 rows x 8 float4
            int idx = l * 256 + tid;
            int r = idx >> 3, c = idx & 7;
            cp_async16(as + r * KST + c * 4, A + (size_t)(rowBase + r) * K + k0 + c * 4);
        }
        #pragma unroll
        for (int l = 0; l < 8; l++) {          // B: 256 rows x 8 float4
            int idx = l * 256 + tid;
            int r = idx >> 3, c = idx & 7;
            cp_async16(bs + r * KST + c * 4, Bm + (size_t)(colBase + r) * K + k0 + c * 4);
        }
    };

    const int T = K / BK;
    #pragma unroll
    for (int s = 0; s < STAGES - 1; s++) { prefetch(s * BK, s); cp_commit(); }

    for (int t = 0; t < T; t++) {
        cp_wait<STAGES - 2>();
        __syncthreads();
        if (t + STAGES - 1 < T) prefetch((t + STAGES - 1) * BK, (t + STAGES - 1) % STAGES);
        cp_commit();   // always commit (keeps group-indexing aligned at the tail)

        const unsigned* as = (const unsigned*)(As + (t % STAGES) * BM * KST) + (wm * 64) * KST;
        const unsigned* bs = (const unsigned*)(Bs + (t % STAGES) * BN * KST) + (wn * 64) * KST;

        #pragma unroll
        for (int kk = 0; kk < BK; kk += 8) {
            unsigned af[4][4], bf[8][2];
            #pragma unroll
            for (int mi = 0; mi < 4; mi++) {
                int base = (mi * 16 + qr) * KST + kk + qt;
                af[mi][0] = as[base];
                af[mi][1] = as[base + 8 * KST];
                af[mi][2] = as[base + 4];
                af[mi][3] = as[base + 8 * KST + 4];
            }
            #pragma unroll
            for (int ni = 0; ni < 8; ni++) {
                int base = (ni * 8 + qr) * KST + kk + qt;
                bf[ni][0] = bs[base];
                bf[ni][1] = bs[base + 4];
            }
            #pragma unroll
            for (int mi = 0; mi < 4; mi++)
                #pragma unroll
                for (int ni = 0; ni < 8; ni++)
                    mma_tf32(acc[mi][ni], af[mi], bf[ni]);
        }
    }

    // epilogue
    #pragma unroll
    for (int mi = 0; mi < 4; mi++) {
        int r0 = rowBase + wm * 64 + mi * 16 + qr;
        #pragma unroll
        for (int ni = 0; ni < 8; ni++) {
            int cc = colBase + wn * 64 + ni * 8 + qt * 2;
            float b0 = bias[cc], b1 = bias[cc + 1];
            float v0 = acc[mi][ni][0] + b0;
            float v1 = acc[mi][ni][1] + b1;
            float v2 = acc[mi][ni][2] + b0;
            float v3 = acc[mi][ni][3] + b1;
            if (RES) {
                v0 += res[(size_t)r0 * N + cc];
                v1 += res[(size_t)r0 * N + cc + 1];
                v2 += res[(size_t)(r0 + 8) * N + cc];
                v3 += res[(size_t)(r0 + 8) * N + cc + 1];
            }
            if (ACT == 1) { v0 = gelu_f(v0); v1 = gelu_f(v1); v2 = gelu_f(v2); v3 = gelu_f(v3); }
            if (RND) { v0 = rnd_tf32(v0); v1 = rnd_tf32(v1); v2 = rnd_tf32(v2); v3 = rnd_tf32(v3); }
            *(float2*)(C + (size_t)r0 * N + cc)       = make_float2(v0, v1);
            *(float2*)(C + (size_t)(r0 + 8) * N + cc) = make_float2(v2, v3);
        }
    }
}

// ---------------- Tensor-core fused attention ----------------
// grid (S/64, H, B), 256 threads (8 warps: 4 row-groups x 2 col-groups).
// Per 64-chunk: S = Q*K^T (mma), P = exp(mask? S : -0.01) -> smem, O += P*V (mma).
// All mma inputs are pre-rounded tf32 values => in-mma truncation is lossless.
#define QS_ST 68
#define VS_ST 72
#define ATTN_SMEM ((64*68 /*Q*/ + 2*64*68 /*K*/ + 2*64*72 /*V*/ + 64*68 /*P*/ + 2*64*68 /*mask*/) * 4)

__global__ __launch_bounds__(256) void attn_mma(const float* __restrict__ Q,
                                                const float* __restrict__ K,
                                                const float* __restrict__ V,
                                                const int* __restrict__ mask,
                                                float* __restrict__ O)
{
    extern __shared__ float sm[];
    float* Qs = sm;                      // [64][68]
    float* Ks = sm + 4352;               // [2][64][68]
    float* Vs = sm + 13056;              // [2][64][72]
    float* Ps = sm + 22272;              // [64][68]
    int*   Ms = (int*)(sm + 26624);      // [2][64][68]

    const int qt_ = blockIdx.x, h = blockIdx.y, b = blockIdx.z;
    const int q0 = qt_ * 64;
    const int tid = threadIdx.x;
    const int warp = tid >> 5, lane = tid & 31;
    const int wm = warp >> 1, wn = warp & 1;
    const int qr = lane >> 2, qt = lane & 3;

    // load Q tile (scaled by 1/sqrt(HD)=0.125, exact power of two)
    #pragma unroll
    for (int l = 0; l < 4; l++) {
        int i = l * 256 + tid;
        int r = i >> 4, c = (i & 15) * 4;
        float4 v = *(const float4*)(Q + (size_t)(b*Sz + q0 + r) * Ez + h*HDz + c);
        float* d = Qs + r * QS_ST + c;
        d[0] = v.x * 0.125f; d[1] = v.y * 0.125f;
        d[2] = v.z * 0.125f; d[3] = v.w * 0.125f;
    }

    auto prefetch = [&](int t, int buf) {
        int k0 = t * 64;
        #pragma unroll
        for (int l = 0; l < 4; l++) {
            int idx = l * 256 + tid;
            int r = idx >> 4, c = (idx & 15) * 4;
            cp_async16(Ks + buf*4352 + r*QS_ST + c, K + (size_t)(b*Sz + k0 + r) * Ez + h*HDz + c);
            cp_async16(Vs + buf*4608 + r*VS_ST + c, V + (size_t)(b*Sz + k0 + r) * Ez + h*HDz + c);
            cp_async16(Ms + buf*4352 + r*QS_ST + c, mask + (size_t)(b*Sz + q0 + r) * Sz + k0 + c);
        }
    };

    prefetch(0, 0); cp_commit();

    float acc[4][4];
    #pragma unroll
    for (int j = 0; j < 4; j++)
        #pragma unroll
        for (int r = 0; r < 4; r++) acc[j][r] = 0.0f;
    float rs0 = 0.f, rs1 = 0.f;
    const float EM = 0.99004983374916805f;   // exp(-0.01)

    for (int t = 0; t < Sz/64; t++) {
        int buf = t & 1;
        cp_wait<0>();
        __syncthreads();
        if (t + 1 < Sz/64) { prefetch(t + 1, buf ^ 1); cp_commit(); }

        // ---- scores ----
        const unsigned* qsb = (const unsigned*)(Qs + (wm*16) * QS_ST);
        const unsigned* ksb = (const unsigned*)(Ks + buf*4352 + (wn*32) * QS_ST);
        float sc[4][4];
        #pragma unroll
        for (int j = 0; j < 4; j++)
            #pragma unroll
            for (int r = 0; r < 4; r++) sc[j][r] = 0.0f;

        #pragma unroll
        for (int kk = 0; kk < 64; kk += 8) {
            unsigned af[4];
            af[0] = qsb[qr * QS_ST + kk + qt];
            af[1] = qsb[(qr + 8) * QS_ST + kk + qt];
            af[2] = qsb[qr * QS_ST + kk + qt + 4];
            af[3] = qsb[(qr + 8) * QS_ST + kk + qt + 4];
            #pragma unroll
            for (int j = 0; j < 4; j++) {
                unsigned bf[2];
                bf[0] = ksb[(j*8 + qr) * QS_ST + kk + qt];
                bf[1] = ksb[(j*8 + qr) * QS_ST + kk + qt + 4];
                mma_tf32(sc[j], af, bf);
            }
        }

        // ---- mask + exp -> P (tf32-rounded), accumulate row sums ----
        const int mrow0 = (wm*16 + qr) * QS_ST;
        const int mrow1 = (wm*16 + qr + 8) * QS_ST;
        const int* Mb = Ms + buf * 4352;
        #pragma unroll
        for (int j = 0; j < 4; j++) {
            int cc = wn*32 + j*8 + 2*qt;
            int2 m0 = *(const int2*)(Mb + mrow0 + cc);
            int2 m1 = *(const int2*)(Mb + mrow1 + cc);
            float p00 = m0.x ? __expf(sc[j][0]) : EM;
            float p01 = m0.y ? __expf(sc[j][1]) : EM;
            float p10 = m1.x ? __expf(sc[j][2]) : EM;
            float p11 = m1.y ? __expf(sc[j][3]) : EM;
            rs0 += p00 + p01;
            rs1 += p10 + p11;
            *(float2*)(Ps + mrow0 + cc) = make_float2(rnd_tf32(p00), rnd_tf32(p01));
            *(float2*)(Ps + mrow1 + cc) = make_float2(rnd_tf32(p10), rnd_tf32(p11));
        }
        __syncthreads();

        // ---- O += P * V ----
        const unsigned* psb = (const unsigned*)(Ps + (wm*16) * QS_ST);
        const unsigned* vsb = (const unsigned*)(Vs + buf*4608 + wn*32);
        #pragma unroll
        for (int kk = 0; kk < 64; kk += 8) {
            unsigned af[4];
            af[0] = psb[qr * QS_ST + kk + qt];
            af[1] = psb[(qr + 8) * QS_ST + kk + qt];
            af[2] = psb[qr * QS_ST + kk + qt + 4];
            af[3] = psb[(qr + 8) * QS_ST + kk + qt + 4];
            #pragma unroll
            for (int j = 0; j < 4; j++) {
                unsigned bf[2];
                bf[0] = vsb[(kk + qt) * VS_ST + j*8 + qr];
                bf[1] = vsb[(kk + qt + 4) * VS_ST + j*8 + qr];
                mma_tf32(acc[j], af, bf);
            }
        }
        __syncthreads();
    }

    // ---- row sums: reduce over qt lanes, then across wn via smem ----
    rs0 += __shfl_xor_sync(0xffffffffu, rs0, 1);
    rs0 += __shfl_xor_sync(0xffffffffu, rs0, 2);
    rs1 += __shfl_xor_sync(0xffffffffu, rs1, 1);
    rs1 += __shfl_xor_sync(0xffffffffu, rs1, 2);
    if (qt == 0) {
        Ps[(wm*16 + qr) * 2 + wn]     = rs0;
        Ps[(wm*16 + qr + 8) * 2 + wn] = rs1;
    }
    __syncthreads();
    float inv0 = 1.0f / (Ps[(wm*16 + qr) * 2 + 0]     + Ps[(wm*16 + qr) * 2 + 1]);
    float inv1 = 1.0f / (Ps[(wm*16 + qr + 8) * 2 + 0] + Ps[(wm*16 + qr + 8) * 2 + 1]);

    // ---- write O (tf32-rounded: feeds Wo GEMM) ----
    const size_t row0 = (size_t)(b*Sz + q0 + wm*16 + qr);
    #pragma unroll
    for (int j = 0; j < 4; j++) {
        int cc = h*HDz + wn*32 + j*8 + 2*qt;
        *(float2*)(O + row0 * Ez + cc)       = make_float2(rnd_tf32(acc[j][0] * inv0), rnd_tf32(acc[j][1] * inv0));
        *(float2*)(O + (row0 + 8) * Ez + cc) = make_float2(rnd_tf32(acc[j][2] * inv1), rnd_tf32(acc[j][3] * inv1));
    }
}

// ---------------- launch ----------------
extern "C" void kernel_launch(void* const* d_in, const int* in_sizes, int n_in,
                              void* d_out, int out_size)
{
    const float* x   = (const float*)d_in[0];
    const int*   msk = (const int*)  d_in[1];
    const float* Wq  = (const float*)d_in[2];
    const float* bq  = (const float*)d_in[3];
    const float* Wk  = (const float*)d_in[4];
    const float* bk  = (const float*)d_in[5];
    const float* Wv  = (const float*)d_in[6];
    const float* bv  = (const float*)d_in[7];
    const float* Wo  = (const float*)d_in[8];
    const float* bo  = (const float*)d_in[9];
    const float* W1  = (const float*)d_in[10];
    const float* b1  = (const float*)d_in[11];
    const float* W2  = (const float*)d_in[12];
    const float* b2  = (const float*)d_in[13];
    const float* g1  = (const float*)d_in[14];
    const float* be1 = (const float*)d_in[15];
    const float* g2  = (const float*)d_in[16];
    const float* be2 = (const float*)d_in[17];
    float* out = (float*)d_out;

    float *nx, *q, *k, *v, *o, *x1, *nx2, *h1;
    float *wq, *wk, *wv, *wo, *w1, *w2;
    cudaGetSymbolAddress((void**)&nx,  g_nx);
    cudaGetSymbolAddress((void**)&q,   g_q);
    cudaGetSymbolAddress((void**)&k,   g_k);
    cudaGetSymbolAddress((void**)&v,   g_v);
    cudaGetSymbolAddress((void**)&o,   g_o);
    cudaGetSymbolAddress((void**)&x1,  g_x1);
    cudaGetSymbolAddress((void**)&nx2, g_nx2);
    cudaGetSymbolAddress((void**)&h1,  g_h1);
    cudaGetSymbolAddress((void**)&wq,  g_wq);
    cudaGetSymbolAddress((void**)&wk,  g_wk);
    cudaGetSymbolAddress((void**)&wv,  g_wv);
    cudaGetSymbolAddress((void**)&wo,  g_wo);
    cudaGetSymbolAddress((void**)&w1,  g_w1);
    cudaGetSymbolAddress((void**)&w2,  g_w2);

    static bool attr_done = false;
    if (!attr_done) {
        cudaFuncSetAttribute((const void*)gemm_tf32<0,false,true>,  cudaFuncAttributeMaxDynamicSharedMemorySize, GEMM_SMEM);
        cudaFuncSetAttribute((const void*)gemm_tf32<0,true,false>,  cudaFuncAttributeMaxDynamicSharedMemorySize, GEMM_SMEM);
        cudaFuncSetAttribute((const void*)gemm_tf32<1,false,true>,  cudaFuncAttributeMaxDynamicSharedMemorySize, GEMM_SMEM);
        cudaFuncSetAttribute((const void*)attn_mma, cudaFuncAttributeMaxDynamicSharedMemorySize, ATTN_SMEM);
        attr_done = true;
    }

    // 0) round weights to tf32-RNA (so mma truncation is lossless)
    const int nE  = Ez*Ez/4;
    const int nF  = DFFz*Ez/4;
    round_kernel<<<(nE+255)/256, 256>>>(Wq, wq, nE);
    round_kernel<<<(nE+255)/256, 256>>>(Wk, wk, nE);
    round_kernel<<<(nE+255)/256, 256>>>(Wv, wv, nE);
    round_kernel<<<(nE+255)/256, 256>>>(Wo, wo, nE);
    round_kernel<<<(nF+255)/256, 256>>>(W1, w1, nF);
    round_kernel<<<(nF+255)/256, 256>>>(W2, w2, nF);

    dim3 gE(Ez/BN,   Mz/BM);   // (4, 32)
    dim3 gF(DFFz/BN, Mz/BM);   // (16, 32)

    // 1) LN1 (rounded output)
    ln_kernel<<<Mz, 256>>>(x, g1, be1, nx);
    // 2-4) Q, K, V projections (rounded outputs)
    gemm_tf32<0,false,true><<<gE, 256, GEMM_SMEM>>>(nx, wq, bq, nullptr, q, Mz, Ez, Ez);
    gemm_tf32<0,false,true><<<gE, 256, GEMM_SMEM>>>(nx, wk, bk, nullptr, k, Mz, Ez, Ez);
    gemm_tf32<0,false,true><<<gE, 256, GEMM_SMEM>>>(nx, wv, bv, nullptr, v, Mz, Ez, Ez);
    // 5) attention (tensor cores; rounded output)
    attn_mma<<<dim3(Sz/64, Hz, Bz), 256, ATTN_SMEM>>>(q, k, v, msk, o);
    // 6) output projection + residual (full fp32 out)
    gemm_tf32<0,true,false><<<gE, 256, GEMM_SMEM>>>(o, wo, bo, x, x1, Mz, Ez, Ez);
    // 7) LN2 (rounded output)
    ln_kernel<<<Mz, 256>>>(x1, g2, be2, nx2);
    // 8) FFN up + GELU (rounded output)
    gemm_tf32<1,false,true><<<gF, 256, GEMM_SMEM>>>(nx2, w1, b1, nullptr, h1, Mz, DFFz, Ez);
    // 9) FFN down + residual -> out (full fp32)
    gemm_tf32<0,true,false><<<gE, 256, GEMM_SMEM>>>(h1, w2, b2, x1, out, Mz, Ez, DFFz);
}

// round 9
// speedup vs baseline: 5.8732x; 1.7131x over previous
#include <cuda_runtime.h>
#include <cuda_fp16.h>
#include <math.h>

// Shapes (fixed)
#define Bz 4
#define Sz 1024
#define Ez 1024
#define Hz 16
#define HDz 64
#define DFFz 4096
#define Mz (Bz*Sz)   // 4096 rows of activations

// ---------------- scratch (device globals; no allocations) ----------------
__device__ __half g_nx  [Mz*Ez];
__device__ __half g_qkv [(size_t)Mz*3*Ez];
__device__ __half g_o   [Mz*Ez];
__device__ float  g_x1  [Mz*Ez];
__device__ __half g_nx2 [Mz*Ez];
__device__ __half g_h1  [(size_t)Mz*DFFz];
__device__ __half g_wqkv[3*Ez*Ez];
__device__ __half g_wo  [Ez*Ez];
__device__ __half g_w1  [(size_t)DFFz*Ez];
__device__ __half g_w2  [(size_t)Ez*DFFz];
__device__ float  g_bqkv[3*Ez];

// ---------------- helpers ----------------
__device__ __forceinline__ float gelu_f(float x) {
    const float c = 0.7978845608028654f; // sqrt(2/pi)
    float u = c * (x + 0.044715f * x * x * x);
    return 0.5f * x * (1.0f + tanhf(u));
}

__device__ __forceinline__ void mma_f16(float* c, const unsigned* a, const unsigned* b) {
    asm volatile(
        "mma.sync.aligned.m16n8k16.row.col.f32.f16.f16.f32 "
        "{%0,%1,%2,%3}, {%4,%5,%6,%7}, {%8,%9}, {%0,%1,%2,%3};\n"
        : "+f"(c[0]), "+f"(c[1]), "+f"(c[2]), "+f"(c[3])
        : "r"(a[0]), "r"(a[1]), "r"(a[2]), "r"(a[3]),
          "r"(b[0]), "r"(b[1]));
}

__device__ __forceinline__ void ldsm_x4(unsigned& r0, unsigned& r1, unsigned& r2, unsigned& r3, unsigned addr) {
    asm volatile("ldmatrix.sync.aligned.m8n8.x4.shared.b16 {%0,%1,%2,%3}, [%4];\n"
                 : "=r"(r0), "=r"(r1), "=r"(r2), "=r"(r3) : "r"(addr));
}
__device__ __forceinline__ void ldsm_x4_t(unsigned& r0, unsigned& r1, unsigned& r2, unsigned& r3, unsigned addr) {
    asm volatile("ldmatrix.sync.aligned.m8n8.x4.trans.shared.b16 {%0,%1,%2,%3}, [%4];\n"
                 : "=r"(r0), "=r"(r1), "=r"(r2), "=r"(r3) : "r"(addr));
}

__device__ __forceinline__ void cp_async16(void* sdst, const void* gsrc) {
    unsigned s = (unsigned)__cvta_generic_to_shared(sdst);
    asm volatile("cp.async.cg.shared.global [%0], [%1], 16;\n" :: "r"(s), "l"(gsrc));
}
__device__ __forceinline__ void cp_commit() {
    asm volatile("cp.async.commit_group;\n" ::);
}
template<int N>
__device__ __forceinline__ void cp_wait() {
    asm volatile("cp.async.wait_group %0;\n" :: "n"(N));
}

// ---------------- fp32 -> fp16 conversion (weights) ----------------
__global__ __launch_bounds__(256) void cvt_h(const float* __restrict__ in,
                                             __half* __restrict__ out, int n4)
{
    int i = blockIdx.x * 256 + threadIdx.x;
    if (i < n4) {
        float4 v = ((const float4*)in)[i];
        __half2 h0 = __floats2half2_rn(v.x, v.y);
        __half2 h1 = __floats2half2_rn(v.z, v.w);
        *(uint2*)(out + (size_t)i * 4) = make_uint2(*(unsigned*)&h0, *(unsigned*)&h1);
    }
}

__global__ __launch_bounds__(256) void bias3_kernel(const float* __restrict__ a,
                                                    const float* __restrict__ b,
                                                    const float* __restrict__ c,
                                                    float* __restrict__ o)
{
    int i = blockIdx.x * 256 + threadIdx.x;
    if (i < Ez) { o[i] = a[i]; o[i + Ez] = b[i]; o[i + 2*Ez] = c[i]; }
}

// ---------------- LayerNorm (ddof=1, eps added to std); half output ----------------
__global__ __launch_bounds__(256) void ln_kernel(const float* __restrict__ x,
                                                 const float* __restrict__ g,
                                                 const float* __restrict__ be,
                                                 __half* __restrict__ y)
{
    __shared__ float red[32];
    int row = blockIdx.x;
    int tid = threadIdx.x;
    const float4* xr = (const float4*)(x + (size_t)row * Ez);
    float4 v = xr[tid];

    float s = v.x + v.y + v.z + v.w;
    #pragma unroll
    for (int o = 16; o > 0; o >>= 1) s += __shfl_xor_sync(0xffffffffu, s, o);
    if ((tid & 31) == 0) red[tid >> 5] = s;
    __syncthreads();
    float t = (tid < 8) ? red[tid] : 0.0f;
    if (tid < 32) {
        #pragma unroll
        for (int o = 4; o > 0; o >>= 1) t += __shfl_xor_sync(0xffffffffu, t, o);
        if (tid == 0) red[0] = t;
    }
    __syncthreads();
    float mean = red[0] * (1.0f / Ez);
    __syncthreads();

    float dx = v.x - mean, dy = v.y - mean, dz = v.z - mean, dw = v.w - mean;
    float sq = dx*dx + dy*dy + dz*dz + dw*dw;
    #pragma unroll
    for (int o = 16; o > 0; o >>= 1) sq += __shfl_xor_sync(0xffffffffu, sq, o);
    if ((tid & 31) == 0) red[tid >> 5] = sq;
    __syncthreads();
    float t2 = (tid < 8) ? red[tid] : 0.0f;
    if (tid < 32) {
        #pragma unroll
        for (int o = 4; o > 0; o >>= 1) t2 += __shfl_xor_sync(0xffffffffu, t2, o);
        if (tid == 0) red[0] = t2;
    }
    __syncthreads();
    float var = red[0] * (1.0f / (Ez - 1));
    float inv = 1.0f / (sqrtf(var) + 1e-8f);

    float4 gg = ((const float4*)g)[tid];
    float4 bb = ((const float4*)be)[tid];
    __half2 h0 = __floats2half2_rn(gg.x * dx * inv + bb.x, gg.y * dy * inv + bb.y);
    __half2 h1 = __floats2half2_rn(gg.z * dz * inv + bb.z, gg.w * dw * inv + bb.w);
    *(uint2*)(y + (size_t)row * Ez + tid * 4) = make_uint2(*(unsigned*)&h0, *(unsigned*)&h1);
}

// ---------------- FP16 tensor-core GEMM, cp.async 3-stage, ldmatrix fragments ----------------
// C[M,N] = A[M,K] * B[N,K]^T + bias[N] (+res) (+gelu) ; half or float output
// 128x256x64 CTA tile, 8 warps (2x4), 64x64 warp tile.
#define BM 128
#define BN 256
#define BKh 64
#define STH 72      // half stride: 36 words == 4 mod 32 -> conflict-free
#define STAGES 3

#define GEMM_SMEM (STAGES*(BM+BN)*STH*2)

template<int ACT, bool RES, bool HOUT, bool QSC>
__global__ __launch_bounds__(256) void gemm_f16(const __half* __restrict__ A,
                                                const __half* __restrict__ Bw,
                                                const float* __restrict__ bias,
                                                const float* __restrict__ res,
                                                float* __restrict__ Cf,
                                                __half* __restrict__ Ch,
                                                int M, int N, int K)
{
    extern __shared__ __half smem[];
    __half* As = smem;                          // [STAGES][BM][STH]
    __half* Bs = smem + STAGES * BM * STH;      // [STAGES][BN][STH]

    const int tid  = threadIdx.x;
    const int warp = tid >> 5, lane = tid & 31;
    const int wm = warp >> 2, wn = warp & 3;    // 2 x 4, warp tile 64x64
    const int qr = lane >> 2, qt = lane & 3;
    const int lane_r  = lane & 15;
    const int lane_c8 = (lane >> 4) * 8;
    const int rowBase = blockIdx.y * BM;
    const int colBase = blockIdx.x * BN;

    float acc[4][8][4];
    #pragma unroll
    for (int mi = 0; mi < 4; mi++)
        #pragma unroll
        for (int ni = 0; ni < 8; ni++)
            #pragma unroll
            for (int r = 0; r < 4; r++) acc[mi][ni][r] = 0.0f;

    auto prefetch = [&](int k0, int buf) {
        __half* as = As + buf * BM * STH;
        __half* bs = Bs + buf * BN * STH;
        #pragma unroll
        for (int l = 0; l < 4; l++) {          // A: 128 rows x 8 16B-chunks
            int idx = l * 256 + tid;
            int r = idx >> 3, c = (idx & 7) * 8;
            cp_async16(as + r * STH + c, A + (size_t)(rowBase + r) * K + k0 + c);
        }
        #pragma unroll
        for (int l = 0; l < 8; l++) {          // B: 256 rows x 8 chunks
            int idx = l * 256 + tid;
            int r = idx >> 3, c = (idx & 7) * 8;
            cp_async16(bs + r * STH + c, Bw + (size_t)(colBase + r) * K + k0 + c);
        }
    };

    const int T = K / BKh;
    #pragma unroll
    for (int s = 0; s < STAGES - 1; s++) { prefetch(s * BKh, s); cp_commit(); }

    for (int t = 0; t < T; t++) {
        cp_wait<STAGES - 2>();
        __syncthreads();
        if (t + STAGES - 1 < T) prefetch((t + STAGES - 1) * BKh, (t + STAGES - 1) % STAGES);
        cp_commit();

        unsigned a_base = (unsigned)__cvta_generic_to_shared(
            As + (t % STAGES) * BM * STH + (wm * 64 + lane_r) * STH + lane_c8);
        unsigned b_base = (unsigned)__cvta_generic_to_shared(
            Bs + (t % STAGES) * BN * STH + (wn * 64 + lane_r) * STH + lane_c8);

        #pragma unroll
        for (int kk = 0; kk < BKh; kk += 16) {
            unsigned af[4][4], bf[8][2];
            #pragma unroll
            for (int mi = 0; mi < 4; mi++)
                ldsm_x4(af[mi][0], af[mi][1], af[mi][2], af[mi][3],
                        a_base + (mi * 16 * STH + kk) * 2);
            #pragma unroll
            for (int nt = 0; nt < 4; nt++) {
                unsigned r0, r1, r2, r3;
                ldsm_x4(r0, r1, r2, r3, b_base + (nt * 16 * STH + kk) * 2);
                bf[nt*2][0] = r0; bf[nt*2][1] = r2;      // rows n0..n0+7: {k0-7, k8-15}
                bf[nt*2+1][0] = r1; bf[nt*2+1][1] = r3;  // rows n0+8..15
            }
            #pragma unroll
            for (int mi = 0; mi < 4; mi++)
                #pragma unroll
                for (int ni = 0; ni < 8; ni++)
                    mma_f16(acc[mi][ni], af[mi], bf[ni]);
        }
    }

    // epilogue
    const float sc = (QSC && colBase < Ez) ? 0.125f : 1.0f;
    #pragma unroll
    for (int mi = 0; mi < 4; mi++) {
        int r0 = rowBase + wm * 64 + mi * 16 + qr;
        #pragma unroll
        for (int ni = 0; ni < 8; ni++) {
            int cc = colBase + wn * 64 + ni * 8 + qt * 2;
            float b0 = bias[cc], b1 = bias[cc + 1];
            float v0 = acc[mi][ni][0] + b0;
            float v1 = acc[mi][ni][1] + b1;
            float v2 = acc[mi][ni][2] + b0;
            float v3 = acc[mi][ni][3] + b1;
            if (RES) {
                v0 += res[(size_t)r0 * N + cc];
                v1 += res[(size_t)r0 * N + cc + 1];
                v2 += res[(size_t)(r0 + 8) * N + cc];
                v3 += res[(size_t)(r0 + 8) * N + cc + 1];
            }
            if (ACT == 1) { v0 = gelu_f(v0); v1 = gelu_f(v1); v2 = gelu_f(v2); v3 = gelu_f(v3); }
            if (QSC) { v0 *= sc; v1 *= sc; v2 *= sc; v3 *= sc; }
            if (HOUT) {
                __half2 h01 = __floats2half2_rn(v0, v1);
                __half2 h23 = __floats2half2_rn(v2, v3);
                *(unsigned*)(Ch + (size_t)r0 * N + cc)       = *(unsigned*)&h01;
                *(unsigned*)(Ch + (size_t)(r0 + 8) * N + cc) = *(unsigned*)&h23;
            } else {
                *(float2*)(Cf + (size_t)r0 * N + cc)       = make_float2(v0, v1);
                *(float2*)(Cf + (size_t)(r0 + 8) * N + cc) = make_float2(v2, v3);
            }
        }
    }
}

// ---------------- FP16 tensor-core fused attention ----------------
// grid (S/64, H, B), 256 threads (8 warps: 4 row x 2 col groups), warp tile 16x32.
// q pre-scaled by 0.125 in the QKV GEMM. Masked score = -0.01 (finite), no online softmax.
#define AST 72
#define QKVS (3*Ez)
#define ATTN_SMEM (27648*2 + 2*64*68*4)

__global__ __launch_bounds__(256) void attn_mma(const __half* __restrict__ QKV,
                                                const int* __restrict__ mask,
                                                __half* __restrict__ O)
{
    extern __shared__ __half smh[];
    __half* Qs = smh;                 // [64][72]
    __half* Ks = smh + 4608;          // [2][64][72]
    __half* Vs = smh + 13824;         // [2][64][72]
    __half* Ps = smh + 23040;         // [64][72]
    int*    Ms = (int*)(smh + 27648); // [2][64][68]

    const int qt_ = blockIdx.x, h = blockIdx.y, b = blockIdx.z;
    const int q0 = qt_ * 64;
    const int tid = threadIdx.x;
    const int warp = tid >> 5, lane = tid & 31;
    const int wm = warp >> 1, wn = warp & 1;
    const int qr = lane >> 2, qt = lane & 3;
    const int lane_r  = lane & 15;
    const int lane_c8 = (lane >> 4) * 8;

    const __half* Qg = QKV + h * HDz;
    const __half* Kg = QKV + Ez + h * HDz;
    const __half* Vg = QKV + 2 * Ez + h * HDz;

    // Q tile: 64 rows x 8 chunks
    #pragma unroll
    for (int l = 0; l < 2; l++) {
        int idx = l * 256 + tid;
        int r = idx >> 3, c = (idx & 7) * 8;
        cp_async16(Qs + r * AST + c, Qg + (size_t)(b*Sz + q0 + r) * QKVS + c);
    }

    auto prefetch = [&](int t, int buf) {
        int k0 = t * 64;
        #pragma unroll
        for (int l = 0; l < 2; l++) {
            int idx = l * 256 + tid;
            int r = idx >> 3, c = (idx & 7) * 8;
            cp_async16(Ks + buf*4608 + r*AST + c, Kg + (size_t)(b*Sz + k0 + r) * QKVS + c);
            cp_async16(Vs + buf*4608 + r*AST + c, Vg + (size_t)(b*Sz + k0 + r) * QKVS + c);
        }
        #pragma unroll
        for (int l = 0; l < 4; l++) {        // mask 64 rows x 16 chunks of 4 ints
            int idx = l * 256 + tid;
            int r = idx >> 4, c = (idx & 15) * 4;
            cp_async16(Ms + buf*4352 + r*68 + c, mask + (size_t)(b*Sz + q0 + r) * Sz + k0 + c);
        }
    };

    prefetch(0, 0); cp_commit();

    float acc[4][4];
    #pragma unroll
    for (int j = 0; j < 4; j++)
        #pragma unroll
        for (int r = 0; r < 4; r++) acc[j][r] = 0.0f;
    float rs0 = 0.f, rs1 = 0.f;
    const float EM = 0.99004983374916805f;   // exp(-0.01)

    const unsigned qa_base = (unsigned)__cvta_generic_to_shared(Qs + (wm*16 + lane_r)*AST + lane_c8);
    const unsigned pa_base = (unsigned)__cvta_generic_to_shared(Ps + (wm*16 + lane_r)*AST + lane_c8);

    for (int t = 0; t < Sz/64; t++) {
        int buf = t & 1;
        cp_wait<0>();
        __syncthreads();
        if (t + 1 < Sz/64) { prefetch(t + 1, buf ^ 1); cp_commit(); }

        // ---- scores: warp tile 16 q-rows x 32 k-cols ----
        unsigned kb_base = (unsigned)__cvta_generic_to_shared(
            Ks + buf*4608 + (wn*32 + lane_r)*AST + lane_c8);
        float scs[4][4];
        #pragma unroll
        for (int j = 0; j < 4; j++)
            #pragma unroll
            for (int r = 0; r < 4; r++) scs[j][r] = 0.0f;

        #pragma unroll
        for (int kk = 0; kk < 64; kk += 16) {
            unsigned af[4];
            ldsm_x4(af[0], af[1], af[2], af[3], qa_base + kk * 2);
            #pragma unroll
            for (int nt = 0; nt < 2; nt++) {
                unsigned r0, r1, r2, r3;
                ldsm_x4(r0, r1, r2, r3, kb_base + (nt * 16 * AST + kk) * 2);
                unsigned b0[2] = {r0, r2}, b1[2] = {r1, r3};
                mma_f16(scs[nt*2],   af, b0);
                mma_f16(scs[nt*2+1], af, b1);
            }
        }

        // ---- mask + exp -> P (half), accumulate row sums ----
        const int mr0 = wm*16 + qr, mr1 = mr0 + 8;
        const int* Mb = Ms + buf * 4352;
        #pragma unroll
        for (int j = 0; j < 4; j++) {
            int cc = wn*32 + j*8 + 2*qt;
            int2 m0 = *(const int2*)(Mb + mr0*68 + cc);
            int2 m1 = *(const int2*)(Mb + mr1*68 + cc);
            float p00 = m0.x ? __expf(scs[j][0]) : EM;
            float p01 = m0.y ? __expf(scs[j][1]) : EM;
            float p10 = m1.x ? __expf(scs[j][2]) : EM;
            float p11 = m1.y ? __expf(scs[j][3]) : EM;
            rs0 += p00 + p01;
            rs1 += p10 + p11;
            __half2 hp0 = __floats2half2_rn(p00, p01);
            __half2 hp1 = __floats2half2_rn(p10, p11);
            *(unsigned*)(Ps + mr0*AST + cc) = *(unsigned*)&hp0;
            *(unsigned*)(Ps + mr1*AST + cc) = *(unsigned*)&hp1;
        }
        __syncthreads();

        // ---- O += P * V : warp tile 16 q-rows x 32 d-cols ----
        unsigned vb_base = (unsigned)__cvta_generic_to_shared(
            Vs + buf*4608 + lane_r*AST + wn*32 + lane_c8);
        #pragma unroll
        for (int kk = 0; kk < 64; kk += 16) {
            unsigned af[4];
            ldsm_x4(af[0], af[1], af[2], af[3], pa_base + kk * 2);
            #pragma unroll
            for (int nt = 0; nt < 2; nt++) {
                unsigned r0, r1, r2, r3;
                ldsm_x4_t(r0, r1, r2, r3, vb_base + (kk * AST + nt * 16) * 2);
                unsigned b0[2] = {r0, r1}, b1[2] = {r2, r3};
                mma_f16(acc[nt*2],   af, b0);
                mma_f16(acc[nt*2+1], af, b1);
            }
        }
        __syncthreads();
    }

    // ---- row sums: reduce over qt lanes, then across wn via smem ----
    rs0 += __shfl_xor_sync(0xffffffffu, rs0, 1);
    rs0 += __shfl_xor_sync(0xffffffffu, rs0, 2);
    rs1 += __shfl_xor_sync(0xffffffffu, rs1, 1);
    rs1 += __shfl_xor_sync(0xffffffffu, rs1, 2);
    float* red = (float*)Ms;
    if (qt == 0) {
        red[(wm*16 + qr) * 2 + wn]     = rs0;
        red[(wm*16 + qr + 8) * 2 + wn] = rs1;
    }
    __syncthreads();
    float inv0 = 1.0f / (red[(wm*16 + qr) * 2 + 0]     + red[(wm*16 + qr) * 2 + 1]);
    float inv1 = 1.0f / (red[(wm*16 + qr + 8) * 2 + 0] + red[(wm*16 + qr + 8) * 2 + 1]);

    // ---- write O (half; feeds Wo GEMM) ----
    const size_t row0 = (size_t)(b*Sz + q0 + wm*16 + qr);
    #pragma unroll
    for (int j = 0; j < 4; j++) {
        int cc = h*HDz + wn*32 + j*8 + 2*qt;
        __half2 h0 = __floats2half2_rn(acc[j][0] * inv0, acc[j][1] * inv0);
        __half2 h1 = __floats2half2_rn(acc[j][2] * inv1, acc[j][3] * inv1);
        *(unsigned*)(O + row0 * Ez + cc)       = *(unsigned*)&h0;
        *(unsigned*)(O + (row0 + 8) * Ez + cc) = *(unsigned*)&h1;
    }
}

// ---------------- launch ----------------
extern "C" void kernel_launch(void* const* d_in, const int* in_sizes, int n_in,
                              void* d_out, int out_size)
{
    const float* x   = (const float*)d_in[0];
    const int*   msk = (const int*)  d_in[1];
    const float* Wq  = (const float*)d_in[2];
    const float* bq  = (const float*)d_in[3];
    const float* Wk  = (const float*)d_in[4];
    const float* bk  = (const float*)d_in[5];
    const float* Wv  = (const float*)d_in[6];
    const float* bv  = (const float*)d_in[7];
    const float* Wo  = (const float*)d_in[8];
    const float* bo  = (const float*)d_in[9];
    const float* W1  = (const float*)d_in[10];
    const float* b1  = (const float*)d_in[11];
    const float* W2  = (const float*)d_in[12];
    const float* b2  = (const float*)d_in[13];
    const float* g1  = (const float*)d_in[14];
    const float* be1 = (const float*)d_in[15];
    const float* g2  = (const float*)d_in[16];
    const float* be2 = (const float*)d_in[17];
    float* out = (float*)d_out;

    __half *nx, *qkv, *o, *nx2, *h1, *wqkv, *wo, *w1, *w2;
    float *x1, *bqkv;
    cudaGetSymbolAddress((void**)&nx,   g_nx);
    cudaGetSymbolAddress((void**)&qkv,  g_qkv);
    cudaGetSymbolAddress((void**)&o,    g_o);
    cudaGetSymbolAddress((void**)&x1,   g_x1);
    cudaGetSymbolAddress((void**)&nx2,  g_nx2);
    cudaGetSymbolAddress((void**)&h1,   g_h1);
    cudaGetSymbolAddress((void**)&wqkv, g_wqkv);
    cudaGetSymbolAddress((void**)&wo,   g_wo);
    cudaGetSymbolAddress((void**)&w1,   g_w1);
    cudaGetSymbolAddress((void**)&w2,   g_w2);
    cudaGetSymbolAddress((void**)&bqkv, g_bqkv);

    static bool attr_done = false;
    if (!attr_done) {
        cudaFuncSetAttribute((const void*)gemm_f16<0,false,true,true>,   cudaFuncAttributeMaxDynamicSharedMemorySize, GEMM_SMEM);
        cudaFuncSetAttribute((const void*)gemm_f16<0,true,false,false>,  cudaFuncAttributeMaxDynamicSharedMemorySize, GEMM_SMEM);
        cudaFuncSetAttribute((const void*)gemm_f16<1,false,true,false>,  cudaFuncAttributeMaxDynamicSharedMemorySize, GEMM_SMEM);
        cudaFuncSetAttribute((const void*)attn_mma, cudaFuncAttributeMaxDynamicSharedMemorySize, ATTN_SMEM);
        attr_done = true;
    }

    const int nE4 = Ez*Ez/4;
    const int nF4 = DFFz*Ez/4;

    // 0) weights -> fp16 (RNE); combined QKV weight + bias
    cvt_h<<<(nE4+255)/256, 256>>>(Wq, wqkv,           nE4);
    cvt_h<<<(nE4+255)/256, 256>>>(Wk, wqkv + Ez*Ez,   nE4);
    cvt_h<<<(nE4+255)/256, 256>>>(Wv, wqkv + 2*Ez*Ez, nE4);
    cvt_h<<<(nE4+255)/256, 256>>>(Wo, wo, nE4);
    cvt_h<<<(nF4+255)/256, 256>>>(W1, w1, nF4);
    cvt_h<<<(nF4+255)/256, 256>>>(W2, w2, nF4);
    bias3_kernel<<<4, 256>>>(bq, bk, bv, bqkv);

    dim3 gQKV(3*Ez/BN, Mz/BM);   // (12, 32)
    dim3 gE(Ez/BN,     Mz/BM);   // (4, 32)
    dim3 gF(DFFz/BN,   Mz/BM);   // (16, 32)

    // 1) LN1 (half output)
    ln_kernel<<<Mz, 256>>>(x, g1, be1, nx);
    // 2) fused QKV projection (q pre-scaled by 0.125)
    gemm_f16<0,false,true,true><<<gQKV, 256, GEMM_SMEM>>>(nx, wqkv, bqkv, nullptr, nullptr, qkv, Mz, 3*Ez, Ez);
    // 3) attention
    attn_mma<<<dim3(Sz/64, Hz, Bz), 256, ATTN_SMEM>>>(qkv, msk, o);
    // 4) output projection + residual (fp32 out)
    gemm_f16<0,true,false,false><<<gE, 256, GEMM_SMEM>>>(o, wo, bo, x, x1, nullptr, Mz, Ez, Ez);
    // 5) LN2 (half output)
    ln_kernel<<<Mz, 256>>>(x1, g2, be2, nx2);
    // 6) FFN up + GELU (half out)
    gemm_f16<1,false,true,false><<<gF, 256, GEMM_SMEM>>>(nx2, w1, b1, nullptr, nullptr, h1, Mz, DFFz, Ez);
    // 7) FFN down + residual -> out (fp32)
    gemm_f16<0,true,false,false><<<gE, 256, GEMM_SMEM>>>(h1, w2, b2, x1, out, nullptr, Mz, Ez, DFFz);
}

// round 10
// speedup vs baseline: 6.6222x; 1.1275x over previous
#include <cuda_runtime.h>
#include <cuda_fp16.h>
#include <math.h>

// Shapes (fixed)
#define Bz 4
#define Sz 1024
#define Ez 1024
#define Hz 16
#define HDz 64
#define DFFz 4096
#define Mz (Bz*Sz)   // 4096 rows of activations

// ---------------- scratch (device globals; no allocations) ----------------
__device__ __half g_nx  [Mz*Ez];
__device__ __half g_qkv [(size_t)Mz*3*Ez];
__device__ __half g_o   [Mz*Ez];
__device__ float  g_x1  [Mz*Ez];
__device__ __half g_nx2 [Mz*Ez];
__device__ __half g_h1  [(size_t)Mz*DFFz];
__device__ __half g_wqkv[3*Ez*Ez];
__device__ __half g_wo  [Ez*Ez];
__device__ __half g_w1  [(size_t)DFFz*Ez];
__device__ __half g_w2  [(size_t)Ez*DFFz];
__device__ float  g_bqkv[3*Ez];

// ---------------- helpers ----------------
__device__ __forceinline__ float gelu_f(float x) {
    const float c = 0.7978845608028654f; // sqrt(2/pi)
    float u = c * (x + 0.044715f * x * x * x);
    return 0.5f * x * (1.0f + tanhf(u));
}

__device__ __forceinline__ void mma_f16(float* c, const unsigned* a, const unsigned* b) {
    asm volatile(
        "mma.sync.aligned.m16n8k16.row.col.f32.f16.f16.f32 "
        "{%0,%1,%2,%3}, {%4,%5,%6,%7}, {%8,%9}, {%0,%1,%2,%3};\n"
        : "+f"(c[0]), "+f"(c[1]), "+f"(c[2]), "+f"(c[3])
        : "r"(a[0]), "r"(a[1]), "r"(a[2]), "r"(a[3]),
          "r"(b[0]), "r"(b[1]));
}

__device__ __forceinline__ void ldsm_x4(unsigned& r0, unsigned& r1, unsigned& r2, unsigned& r3, unsigned addr) {
    asm volatile("ldmatrix.sync.aligned.m8n8.x4.shared.b16 {%0,%1,%2,%3}, [%4];\n"
                 : "=r"(r0), "=r"(r1), "=r"(r2), "=r"(r3) : "r"(addr));
}
__device__ __forceinline__ void ldsm_x4_t(unsigned& r0, unsigned& r1, unsigned& r2, unsigned& r3, unsigned addr) {
    asm volatile("ldmatrix.sync.aligned.m8n8.x4.trans.shared.b16 {%0,%1,%2,%3}, [%4];\n"
                 : "=r"(r0), "=r"(r1), "=r"(r2), "=r"(r3) : "r"(addr));
}

__device__ __forceinline__ void cp_async16(void* sdst, const void* gsrc) {
    unsigned s = (unsigned)__cvta_generic_to_shared(sdst);
    asm volatile("cp.async.cg.shared.global [%0], [%1], 16;\n" :: "r"(s), "l"(gsrc));
}
__device__ __forceinline__ void cp_commit() {
    asm volatile("cp.async.commit_group;\n" ::);
}
template<int N>
__device__ __forceinline__ void cp_wait() {
    asm volatile("cp.async.wait_group %0;\n" :: "n"(N));
}

// ---------------- fp32 -> fp16 conversion (weights) ----------------
__global__ __launch_bounds__(256) void cvt_h(const float* __restrict__ in,
                                             __half* __restrict__ out, int n4)
{
    int i = blockIdx.x * 256 + threadIdx.x;
    if (i < n4) {
        float4 v = ((const float4*)in)[i];
        __half2 h0 = __floats2half2_rn(v.x, v.y);
        __half2 h1 = __floats2half2_rn(v.z, v.w);
        *(uint2*)(out + (size_t)i * 4) = make_uint2(*(unsigned*)&h0, *(unsigned*)&h1);
    }
}

__global__ __launch_bounds__(256) void bias3_kernel(const float* __restrict__ a,
                                                    const float* __restrict__ b,
                                                    const float* __restrict__ c,
                                                    float* __restrict__ o)
{
    int i = blockIdx.x * 256 + threadIdx.x;
    if (i < Ez) { o[i] = a[i]; o[i + Ez] = b[i]; o[i + 2*Ez] = c[i]; }
}

// ---------------- LayerNorm (ddof=1, eps added to std); half output ----------------
__global__ __launch_bounds__(256) void ln_kernel(const float* __restrict__ x,
                                                 const float* __restrict__ g,
                                                 const float* __restrict__ be,
                                                 __half* __restrict__ y)
{
    __shared__ float red[32];
    int row = blockIdx.x;
    int tid = threadIdx.x;
    const float4* xr = (const float4*)(x + (size_t)row * Ez);
    float4 v = xr[tid];

    float s = v.x + v.y + v.z + v.w;
    #pragma unroll
    for (int o = 16; o > 0; o >>= 1) s += __shfl_xor_sync(0xffffffffu, s, o);
    if ((tid & 31) == 0) red[tid >> 5] = s;
    __syncthreads();
    float t = (tid < 8) ? red[tid] : 0.0f;
    if (tid < 32) {
        #pragma unroll
        for (int o = 4; o > 0; o >>= 1) t += __shfl_xor_sync(0xffffffffu, t, o);
        if (tid == 0) red[0] = t;
    }
    __syncthreads();
    float mean = red[0] * (1.0f / Ez);
    __syncthreads();

    float dx = v.x - mean, dy = v.y - mean, dz = v.z - mean, dw = v.w - mean;
    float sq = dx*dx + dy*dy + dz*dz + dw*dw;
    #pragma unroll
    for (int o = 16; o > 0; o >>= 1) sq += __shfl_xor_sync(0xffffffffu, sq, o);
    if ((tid & 31) == 0) red[tid >> 5] = sq;
    __syncthreads();
    float t2 = (tid < 8) ? red[tid] : 0.0f;
    if (tid < 32) {
        #pragma unroll
        for (int o = 4; o > 0; o >>= 1) t2 += __shfl_xor_sync(0xffffffffu, t2, o);
        if (tid == 0) red[0] = t2;
    }
    __syncthreads();
    float var = red[0] * (1.0f / (Ez - 1));
    float inv = 1.0f / (sqrtf(var) + 1e-8f);

    float4 gg = ((const float4*)g)[tid];
    float4 bb = ((const float4*)be)[tid];
    __half2 h0 = __floats2half2_rn(gg.x * dx * inv + bb.x, gg.y * dy * inv + bb.y);
    __half2 h1 = __floats2half2_rn(gg.z * dz * inv + bb.z, gg.w * dw * inv + bb.w);
    *(uint2*)(y + (size_t)row * Ez + tid * 4) = make_uint2(*(unsigned*)&h0, *(unsigned*)&h1);
}

// ---------------- FP16 tensor-core GEMM, cp.async 3-stage, ldmatrix, 2 CTA/SM ----------------
// C[M,N] = A[M,K] * B[N,K]^T + bias[N] (+res) (+gelu) ; half or float output
// 128x128x64 CTA tile, 8 warps (4x2), warp tile 32x64.
#define BM 128
#define BNt 128
#define BKh 64
#define STH 72      // half stride: 36 words == 4 mod 32 -> conflict-free
#define STAGES 3

#define GEMM_SMEM (STAGES*(BM+BNt)*STH*2)

template<int ACT, bool RES, bool HOUT, bool QSC>
__global__ __launch_bounds__(256, 2) void gemm_f16(const __half* __restrict__ A,
                                                   const __half* __restrict__ Bw,
                                                   const float* __restrict__ bias,
                                                   const float* __restrict__ res,
                                                   float* __restrict__ Cf,
                                                   __half* __restrict__ Ch,
                                                   int M, int N, int K)
{
    extern __shared__ __half smem[];
    __half* As = smem;                          // [STAGES][BM][STH]
    __half* Bs = smem + STAGES * BM * STH;      // [STAGES][BNt][STH]

    const int tid  = threadIdx.x;
    const int warp = tid >> 5, lane = tid & 31;
    const int wm = warp >> 1, wn = warp & 1;    // 4 x 2, warp tile 32x64
    const int qr = lane >> 2, qt = lane & 3;
    const int lane_r  = lane & 15;
    const int lane_c8 = (lane >> 4) * 8;
    const int rowBase = blockIdx.y * BM;
    const int colBase = blockIdx.x * BNt;

    float acc[2][8][4];
    #pragma unroll
    for (int mi = 0; mi < 2; mi++)
        #pragma unroll
        for (int ni = 0; ni < 8; ni++)
            #pragma unroll
            for (int r = 0; r < 4; r++) acc[mi][ni][r] = 0.0f;

    auto prefetch = [&](int k0, int buf) {
        __half* as = As + buf * BM * STH;
        __half* bs = Bs + buf * BNt * STH;
        #pragma unroll
        for (int l = 0; l < 4; l++) {          // A: 128 rows x 8 16B-chunks
            int idx = l * 256 + tid;
            int r = idx >> 3, c = (idx & 7) * 8;
            cp_async16(as + r * STH + c, A + (size_t)(rowBase + r) * K + k0 + c);
        }
        #pragma unroll
        for (int l = 0; l < 4; l++) {          // B: 128 rows x 8 chunks
            int idx = l * 256 + tid;
            int r = idx >> 3, c = (idx & 7) * 8;
            cp_async16(bs + r * STH + c, Bw + (size_t)(colBase + r) * K + k0 + c);
        }
    };

    const int T = K / BKh;
    #pragma unroll
    for (int s = 0; s < STAGES - 1; s++) { prefetch(s * BKh, s); cp_commit(); }

    for (int t = 0; t < T; t++) {
        cp_wait<STAGES - 2>();
        __syncthreads();
        if (t + STAGES - 1 < T) prefetch((t + STAGES - 1) * BKh, (t + STAGES - 1) % STAGES);
        cp_commit();

        unsigned a_base = (unsigned)__cvta_generic_to_shared(
            As + (t % STAGES) * BM * STH + (wm * 32 + lane_r) * STH + lane_c8);
        unsigned b_base = (unsigned)__cvta_generic_to_shared(
            Bs + (t % STAGES) * BNt * STH + (wn * 64 + lane_r) * STH + lane_c8);

        #pragma unroll
        for (int kk = 0; kk < BKh; kk += 16) {
            unsigned af[2][4], bf[8][2];
            #pragma unroll
            for (int mi = 0; mi < 2; mi++)
                ldsm_x4(af[mi][0], af[mi][1], af[mi][2], af[mi][3],
                        a_base + (mi * 16 * STH + kk) * 2);
            #pragma unroll
            for (int nt = 0; nt < 4; nt++) {
                unsigned r0, r1, r2, r3;
                ldsm_x4(r0, r1, r2, r3, b_base + (nt * 16 * STH + kk) * 2);
                bf[nt*2][0] = r0; bf[nt*2][1] = r2;      // rows n0..n0+7: {k0-7, k8-15}
                bf[nt*2+1][0] = r1; bf[nt*2+1][1] = r3;  // rows n0+8..15
            }
            #pragma unroll
            for (int mi = 0; mi < 2; mi++)
                #pragma unroll
                for (int ni = 0; ni < 8; ni++)
                    mma_f16(acc[mi][ni], af[mi], bf[ni]);
        }
    }

    // epilogue
    const float sc = (QSC && colBase < Ez) ? 0.125f : 1.0f;
    #pragma unroll
    for (int mi = 0; mi < 2; mi++) {
        int r0 = rowBase + wm * 32 + mi * 16 + qr;
        #pragma unroll
        for (int ni = 0; ni < 8; ni++) {
            int cc = colBase + wn * 64 + ni * 8 + qt * 2;
            float b0 = bias[cc], b1 = bias[cc + 1];
            float v0 = acc[mi][ni][0] + b0;
            float v1 = acc[mi][ni][1] + b1;
            float v2 = acc[mi][ni][2] + b0;
            float v3 = acc[mi][ni][3] + b1;
            if (RES) {
                v0 += res[(size_t)r0 * N + cc];
                v1 += res[(size_t)r0 * N + cc + 1];
                v2 += res[(size_t)(r0 + 8) * N + cc];
                v3 += res[(size_t)(r0 + 8) * N + cc + 1];
            }
            if (ACT == 1) { v0 = gelu_f(v0); v1 = gelu_f(v1); v2 = gelu_f(v2); v3 = gelu_f(v3); }
            if (QSC) { v0 *= sc; v1 *= sc; v2 *= sc; v3 *= sc; }
            if (HOUT) {
                __half2 h01 = __floats2half2_rn(v0, v1);
                __half2 h23 = __floats2half2_rn(v2, v3);
                *(unsigned*)(Ch + (size_t)r0 * N + cc)       = *(unsigned*)&h01;
                *(unsigned*)(Ch + (size_t)(r0 + 8) * N + cc) = *(unsigned*)&h23;
            } else {
                *(float2*)(Cf + (size_t)r0 * N + cc)       = make_float2(v0, v1);
                *(float2*)(Cf + (size_t)(r0 + 8) * N + cc) = make_float2(v2, v3);
            }
        }
    }
}

// ---------------- FP16 tensor-core fused attention ----------------
// grid (S/64, H, B), 256 threads (8 warps: 4 row x 2 col groups), warp tile 16x32.
// q pre-scaled by 0.125 in the QKV GEMM. Masked score = -0.01 (finite), no online softmax.
#define AST 72
#define QKVS (3*Ez)
#define ATTN_SMEM (27648*2 + 2*64*68*4)

__global__ __launch_bounds__(256) void attn_mma(const __half* __restrict__ QKV,
                                                const int* __restrict__ mask,
                                                __half* __restrict__ O)
{
    extern __shared__ __half smh[];
    __half* Qs = smh;                 // [64][72]
    __half* Ks = smh + 4608;          // [2][64][72]
    __half* Vs = smh + 13824;         // [2][64][72]
    __half* Ps = smh + 23040;         // [64][72]
    int*    Ms = (int*)(smh + 27648); // [2][64][68]

    const int qt_ = blockIdx.x, h = blockIdx.y, b = blockIdx.z;
    const int q0 = qt_ * 64;
    const int tid = threadIdx.x;
    const int warp = tid >> 5, lane = tid & 31;
    const int wm = warp >> 1, wn = warp & 1;
    const int qr = lane >> 2, qt = lane & 3;
    const int lane_r  = lane & 15;
    const int lane_c8 = (lane >> 4) * 8;

    const __half* Qg = QKV + h * HDz;
    const __half* Kg = QKV + Ez + h * HDz;
    const __half* Vg = QKV + 2 * Ez + h * HDz;

    // Q tile: 64 rows x 8 chunks
    #pragma unroll
    for (int l = 0; l < 2; l++) {
        int idx = l * 256 + tid;
        int r = idx >> 3, c = (idx & 7) * 8;
        cp_async16(Qs + r * AST + c, Qg + (size_t)(b*Sz + q0 + r) * QKVS + c);
    }

    auto prefetch = [&](int t, int buf) {
        int k0 = t * 64;
        #pragma unroll
        for (int l = 0; l < 2; l++) {
            int idx = l * 256 + tid;
            int r = idx >> 3, c = (idx & 7) * 8;
            cp_async16(Ks + buf*4608 + r*AST + c, Kg + (size_t)(b*Sz + k0 + r) * QKVS + c);
            cp_async16(Vs + buf*4608 + r*AST + c, Vg + (size_t)(b*Sz + k0 + r) * QKVS + c);
        }
        #pragma unroll
        for (int l = 0; l < 4; l++) {        // mask 64 rows x 16 chunks of 4 ints
            int idx = l * 256 + tid;
            int r = idx >> 4, c = (idx & 15) * 4;
            cp_async16(Ms + buf*4352 + r*68 + c, mask + (size_t)(b*Sz + q0 + r) * Sz + k0 + c);
        }
    };

    prefetch(0, 0); cp_commit();

    float acc[4][4];
    #pragma unroll
    for (int j = 0; j < 4; j++)
        #pragma unroll
        for (int r = 0; r < 4; r++) acc[j][r] = 0.0f;
    float rs0 = 0.f, rs1 = 0.f;
    const float EM = 0.99004983374916805f;   // exp(-0.01)

    const unsigned qa_base = (unsigned)__cvta_generic_to_shared(Qs + (wm*16 + lane_r)*AST + lane_c8);
    const unsigned pa_base = (unsigned)__cvta_generic_to_shared(Ps + (wm*16 + lane_r)*AST + lane_c8);

    for (int t = 0; t < Sz/64; t++) {
        int buf = t & 1;
        cp_wait<0>();
        __syncthreads();
        if (t + 1 < Sz/64) { prefetch(t + 1, buf ^ 1); cp_commit(); }

        // ---- scores: warp tile 16 q-rows x 32 k-cols ----
        unsigned kb_base = (unsigned)__cvta_generic_to_shared(
            Ks + buf*4608 + (wn*32 + lane_r)*AST + lane_c8);
        float scs[4][4];
        #pragma unroll
        for (int j = 0; j < 4; j++)
            #pragma unroll
            for (int r = 0; r < 4; r++) scs[j][r] = 0.0f;

        #pragma unroll
        for (int kk = 0; kk < 64; kk += 16) {
            unsigned af[4];
            ldsm_x4(af[0], af[1], af[2], af[3], qa_base + kk * 2);
            #pragma unroll
            for (int nt = 0; nt < 2; nt++) {
                unsigned r0, r1, r2, r3;
                ldsm_x4(r0, r1, r2, r3, kb_base + (nt * 16 * AST + kk) * 2);
                unsigned b0[2] = {r0, r2}, b1[2] = {r1, r3};
                mma_f16(scs[nt*2],   af, b0);
                mma_f16(scs[nt*2+1], af, b1);
            }
        }

        // ---- mask + exp -> P (half), accumulate row sums ----
        const int mr0 = wm*16 + qr, mr1 = mr0 + 8;
        const int* Mb = Ms + buf * 4352;
        #pragma unroll
        for (int j = 0; j < 4; j++) {
            int cc = wn*32 + j*8 + 2*qt;
            int2 m0 = *(const int2*)(Mb + mr0*68 + cc);
            int2 m1 = *(const int2*)(Mb + mr1*68 + cc);
            float p00 = m0.x ? __expf(scs[j][0]) : EM;
            float p01 = m0.y ? __expf(scs[j][1]) : EM;
            float p10 = m1.x ? __expf(scs[j][2]) : EM;
            float p11 = m1.y ? __expf(scs[j][3]) : EM;
            rs0 += p00 + p01;
            rs1 += p10 + p11;
            __half2 hp0 = __floats2half2_rn(p00, p01);
            __half2 hp1 = __floats2half2_rn(p10, p11);
            *(unsigned*)(Ps + mr0*AST + cc) = *(unsigned*)&hp0;
            *(unsigned*)(Ps + mr1*AST + cc) = *(unsigned*)&hp1;
        }
        __syncthreads();

        // ---- O += P * V : warp tile 16 q-rows x 32 d-cols ----
        unsigned vb_base = (unsigned)__cvta_generic_to_shared(
            Vs + buf*4608 + lane_r*AST + wn*32 + lane_c8);
        #pragma unroll
        for (int kk = 0; kk < 64; kk += 16) {
            unsigned af[4];
            ldsm_x4(af[0], af[1], af[2], af[3], pa_base + kk * 2);
            #pragma unroll
            for (int nt = 0; nt < 2; nt++) {
                unsigned r0, r1, r2, r3;
                ldsm_x4_t(r0, r1, r2, r3, vb_base + (kk * AST + nt * 16) * 2);
                unsigned b0[2] = {r0, r1}, b1[2] = {r2, r3};
                mma_f16(acc[nt*2],   af, b0);
                mma_f16(acc[nt*2+1], af, b1);
            }
        }
        __syncthreads();
    }

    // ---- row sums: reduce over qt lanes, then across wn via smem ----
    rs0 += __shfl_xor_sync(0xffffffffu, rs0, 1);
    rs0 += __shfl_xor_sync(0xffffffffu, rs0, 2);
    rs1 += __shfl_xor_sync(0xffffffffu, rs1, 1);
    rs1 += __shfl_xor_sync(0xffffffffu, rs1, 2);
    float* red = (float*)Ms;
    if (qt == 0) {
        red[(wm*16 + qr) * 2 + wn]     = rs0;
        red[(wm*16 + qr + 8) * 2 + wn] = rs1;
    }
    __syncthreads();
    float inv0 = 1.0f / (red[(wm*16 + qr) * 2 + 0]     + red[(wm*16 + qr) * 2 + 1]);
    float inv1 = 1.0f / (red[(wm*16 + qr + 8) * 2 + 0] + red[(wm*16 + qr + 8) * 2 + 1]);

    // ---- write O (half; feeds Wo GEMM) ----
    const size_t row0 = (size_t)(b*Sz + q0 + wm*16 + qr);
    #pragma unroll
    for (int j = 0; j < 4; j++) {
        int cc = h*HDz + wn*32 + j*8 + 2*qt;
        __half2 h0 = __floats2half2_rn(acc[j][0] * inv0, acc[j][1] * inv0);
        __half2 h1 = __floats2half2_rn(acc[j][2] * inv1, acc[j][3] * inv1);
        *(unsigned*)(O + row0 * Ez + cc)       = *(unsigned*)&h0;
        *(unsigned*)(O + (row0 + 8) * Ez + cc) = *(unsigned*)&h1;
    }
}

// ---------------- launch ----------------
extern "C" void kernel_launch(void* const* d_in, const int* in_sizes, int n_in,
                              void* d_out, int out_size)
{
    const float* x   = (const float*)d_in[0];
    const int*   msk = (const int*)  d_in[1];
    const float* Wq  = (const float*)d_in[2];
    const float* bq  = (const float*)d_in[3];
    const float* Wk  = (const float*)d_in[4];
    const float* bk  = (const float*)d_in[5];
    const float* Wv  = (const float*)d_in[6];
    const float* bv  = (const float*)d_in[7];
    const float* Wo  = (const float*)d_in[8];
    const float* bo  = (const float*)d_in[9];
    const float* W1  = (const float*)d_in[10];
    const float* b1  = (const float*)d_in[11];
    const float* W2  = (const float*)d_in[12];
    const float* b2  = (const float*)d_in[13];
    const float* g1  = (const float*)d_in[14];
    const float* be1 = (const float*)d_in[15];
    const float* g2  = (const float*)d_in[16];
    const float* be2 = (const float*)d_in[17];
    float* out = (float*)d_out;

    __half *nx, *qkv, *o, *nx2, *h1, *wqkv, *wo, *w1, *w2;
    float *x1, *bqkv;
    cudaGetSymbolAddress((void**)&nx,   g_nx);
    cudaGetSymbolAddress((void**)&qkv,  g_qkv);
    cudaGetSymbolAddress((void**)&o,    g_o);
    cudaGetSymbolAddress((void**)&x1,   g_x1);
    cudaGetSymbolAddress((void**)&nx2,  g_nx2);
    cudaGetSymbolAddress((void**)&h1,   g_h1);
    cudaGetSymbolAddress((void**)&wqkv, g_wqkv);
    cudaGetSymbolAddress((void**)&wo,   g_wo);
    cudaGetSymbolAddress((void**)&w1,   g_w1);
    cudaGetSymbolAddress((void**)&w2,   g_w2);
    cudaGetSymbolAddress((void**)&bqkv, g_bqkv);

    static cudaStream_t s1 = nullptr;
    static cudaEvent_t ev0 = nullptr, ev1 = nullptr;
    static bool attr_done = false;
    if (!attr_done) {
        cudaFuncSetAttribute((const void*)gemm_f16<0,false,true,true>,   cudaFuncAttributeMaxDynamicSharedMemorySize, GEMM_SMEM);
        cudaFuncSetAttribute((const void*)gemm_f16<0,true,false,false>,  cudaFuncAttributeMaxDynamicSharedMemorySize, GEMM_SMEM);
        cudaFuncSetAttribute((const void*)gemm_f16<1,false,true,false>,  cudaFuncAttributeMaxDynamicSharedMemorySize, GEMM_SMEM);
        cudaFuncSetAttribute((const void*)attn_mma, cudaFuncAttributeMaxDynamicSharedMemorySize, ATTN_SMEM);
        cudaStreamCreateWithFlags(&s1, cudaStreamNonBlocking);
        cudaEventCreateWithFlags(&ev0, cudaEventDisableTiming);
        cudaEventCreateWithFlags(&ev1, cudaEventDisableTiming);
        attr_done = true;
    }

    const int nE4 = Ez*Ez/4;
    const int nF4 = DFFz*Ez/4;

    // fork: convert Wo/W1/W2 on side stream, overlapped with LN1/QKV/attention
    cudaEventRecord(ev0, 0);
    cudaStreamWaitEvent(s1, ev0, 0);
    cvt_h<<<(nE4+255)/256, 256, 0, s1>>>(Wo, wo, nE4);
    cvt_h<<<(nF4+255)/256, 256, 0, s1>>>(W1, w1, nF4);
    cvt_h<<<(nF4+255)/256, 256, 0, s1>>>(W2, w2, nF4);
    cudaEventRecord(ev1, s1);

    // critical path: QKV weights + bias
    cvt_h<<<(nE4+255)/256, 256>>>(Wq, wqkv,           nE4);
    cvt_h<<<(nE4+255)/256, 256>>>(Wk, wqkv + Ez*Ez,   nE4);
    cvt_h<<<(nE4+255)/256, 256>>>(Wv, wqkv + 2*Ez*Ez, nE4);
    bias3_kernel<<<4, 256>>>(bq, bk, bv, bqkv);

    dim3 gQKV(3*Ez/BNt, Mz/BM);   // (24, 32)
    dim3 gE(Ez/BNt,     Mz/BM);   // (8, 32)
    dim3 gF(DFFz/BNt,   Mz/BM);   // (32, 32)

    // 1) LN1 (half output)
    ln_kernel<<<Mz, 256>>>(x, g1, be1, nx);
    // 2) fused QKV projection (q pre-scaled by 0.125)
    gemm_f16<0,false,true,true><<<gQKV, 256, GEMM_SMEM>>>(nx, wqkv, bqkv, nullptr, nullptr, qkv, Mz, 3*Ez, Ez);
    // 3) attention
    attn_mma<<<dim3(Sz/64, Hz, Bz), 256, ATTN_SMEM>>>(qkv, msk, o);
    // join: Wo/W1/W2 conversions must be done
    cudaStreamWaitEvent(0, ev1, 0);
    // 4) output projection + residual (fp32 out)
    gemm_f16<0,true,false,false><<<gE, 256, GEMM_SMEM>>>(o, wo, bo, x, x1, nullptr, Mz, Ez, Ez);
    // 5) LN2 (half output)
    ln_kernel<<<Mz, 256>>>(x1, g2, be2, nx2);
    // 6) FFN up + GELU (half out)
    gemm_f16<1,false,true,false><<<gF, 256, GEMM_SMEM>>>(nx2, w1, b1, nullptr, nullptr, h1, Mz, DFFz, Ez);
    // 7) FFN down + residual -> out (fp32)
    gemm_f16<0,true,false,false><<<gE, 256, GEMM_SMEM>>>(h1, w2, b2, x1, out, nullptr, Mz, Ez, DFFz);
}

// round 13
// speedup vs baseline: 7.1916x; 1.0860x over previous
#include <cuda_runtime.h>
#include <cuda_fp16.h>
#include <math.h>
#include <cstdint>

// Shapes (fixed)
#define Bz 4
#define Sz 1024
#define Ez 1024
#define Hz 16
#define HDz 64
#define DFFz 4096
#define Mz (Bz*Sz)   // 4096 rows of activations

// ---------------- scratch (device globals; no allocations) ----------------
__device__ __half g_nx  [Mz*Ez];
__device__ __half g_qkv [(size_t)Mz*3*Ez];
__device__ __half g_o   [Mz*Ez];
__device__ float  g_x1  [Mz*Ez];
__device__ __half g_nx2 [Mz*Ez];
__device__ __half g_h1  [(size_t)Mz*DFFz];
__device__ __half g_wqkv[3*Ez*Ez];
__device__ __half g_wo  [Ez*Ez];
__device__ __half g_w1  [(size_t)DFFz*Ez];
__device__ __half g_w2  [(size_t)Ez*DFFz];
__device__ float  g_bqkv[3*Ez];
__device__ uint32_t g_pk[Mz*32];      // packed mask bits: [B*S][S/32]

// ---------------- helpers ----------------
__device__ __forceinline__ float gelu_f(float x) {
    const float c = 0.7978845608028654f; // sqrt(2/pi)
    float u = c * (x + 0.044715f * x * x * x);
    return 0.5f * x * (1.0f + tanhf(u));
}

__device__ __forceinline__ void mma_f16(float* c, const unsigned* a, const unsigned* b) {
    asm volatile(
        "mma.sync.aligned.m16n8k16.row.col.f32.f16.f16.f32 "
        "{%0,%1,%2,%3}, {%4,%5,%6,%7}, {%8,%9}, {%0,%1,%2,%3};\n"
        : "+f"(c[0]), "+f"(c[1]), "+f"(c[2]), "+f"(c[3])
        : "r"(a[0]), "r"(a[1]), "r"(a[2]), "r"(a[3]),
          "r"(b[0]), "r"(b[1]));
}

__device__ __forceinline__ void ldsm_x4(unsigned& r0, unsigned& r1, unsigned& r2, unsigned& r3, unsigned addr) {
    asm volatile("ldmatrix.sync.aligned.m8n8.x4.shared.b16 {%0,%1,%2,%3}, [%4];\n"
                 : "=r"(r0), "=r"(r1), "=r"(r2), "=r"(r3) : "r"(addr));
}
__device__ __forceinline__ void ldsm_x4_t(unsigned& r0, unsigned& r1, unsigned& r2, unsigned& r3, unsigned addr) {
    asm volatile("ldmatrix.sync.aligned.m8n8.x4.trans.shared.b16 {%0,%1,%2,%3}, [%4];\n"
                 : "=r"(r0), "=r"(r1), "=r"(r2), "=r"(r3) : "r"(addr));
}

__device__ __forceinline__ void cp_async16(void* sdst, const void* gsrc) {
    unsigned s = (unsigned)__cvta_generic_to_shared(sdst);
    asm volatile("cp.async.cg.shared.global [%0], [%1], 16;\n" :: "r"(s), "l"(gsrc));
}
__device__ __forceinline__ void cp_commit() {
    asm volatile("cp.async.commit_group;\n" ::);
}
template<int N>
__device__ __forceinline__ void cp_wait() {
    asm volatile("cp.async.wait_group %0;\n" :: "n"(N));
}

// ---------------- fp32 -> fp16 conversion (weights) ----------------
__global__ __launch_bounds__(256) void cvt_h(const float* __restrict__ in,
                                             __half* __restrict__ out, int n4)
{
    int i = blockIdx.x * 256 + threadIdx.x;
    if (i < n4) {
        float4 v = ((const float4*)in)[i];
        __half2 h0 = __floats2half2_rn(v.x, v.y);
        __half2 h1 = __floats2half2_rn(v.z, v.w);
        *(uint2*)(out + (size_t)i * 4) = make_uint2(*(unsigned*)&h0, *(unsigned*)&h1);
    }
}

__global__ __launch_bounds__(256) void bias3_kernel(const float* __restrict__ a,
                                                    const float* __restrict__ b,
                                                    const float* __restrict__ c,
                                                    float* __restrict__ o)
{
    int i = blockIdx.x * 256 + threadIdx.x;
    if (i < Ez) { o[i] = a[i]; o[i + Ez] = b[i]; o[i + 2*Ez] = c[i]; }
}

// ---------------- pack mask to bits (1 = keep score, 0 = use -0.01) ----------------
__global__ __launch_bounds__(256) void pack_mask(const int* __restrict__ mask,
                                                 uint32_t* __restrict__ pk)
{
    int row = blockIdx.x;                  // b*S + q
    int lane = threadIdx.x & 31, w = threadIdx.x >> 5;   // 8 warps
    const int* mrow = mask + (size_t)row * Sz;
    #pragma unroll
    for (int it = 0; it < 4; it++) {
        int word = it * 8 + w;
        int v = mrow[word * 32 + lane];
        unsigned bits = __ballot_sync(0xffffffffu, v != 0);
        if (lane == 0) pk[row * 32 + word] = bits;
    }
}

// ---------------- LayerNorm (ddof=1, eps added to std); half output ----------------
__global__ __launch_bounds__(256) void ln_kernel(const float* __restrict__ x,
                                                 const float* __restrict__ g,
                                                 const float* __restrict__ be,
                                                 __half* __restrict__ y)
{
    __shared__ float red[32];
    int row = blockIdx.x;
    int tid = threadIdx.x;
    const float4* xr = (const float4*)(x + (size_t)row * Ez);
    float4 v = xr[tid];

    float s = v.x + v.y + v.z + v.w;
    #pragma unroll
    for (int o = 16; o > 0; o >>= 1) s += __shfl_xor_sync(0xffffffffu, s, o);
    if ((tid & 31) == 0) red[tid >> 5] = s;
    __syncthreads();
    float t = (tid < 8) ? red[tid] : 0.0f;
    if (tid < 32) {
        #pragma unroll
        for (int o = 4; o > 0; o >>= 1) t += __shfl_xor_sync(0xffffffffu, t, o);
        if (tid == 0) red[0] = t;
    }
    __syncthreads();
    float mean = red[0] * (1.0f / Ez);
    __syncthreads();

    float dx = v.x - mean, dy = v.y - mean, dz = v.z - mean, dw = v.w - mean;
    float sq = dx*dx + dy*dy + dz*dz + dw*dw;
    #pragma unroll
    for (int o = 16; o > 0; o >>= 1) sq += __shfl_xor_sync(0xffffffffu, sq, o);
    if ((tid & 31) == 0) red[tid >> 5] = sq;
    __syncthreads();
    float t2 = (tid < 8) ? red[tid] : 0.0f;
    if (tid < 32) {
        #pragma unroll
        for (int o = 4; o > 0; o >>= 1) t2 += __shfl_xor_sync(0xffffffffu, t2, o);
        if (tid == 0) red[0] = t2;
    }
    __syncthreads();
    float var = red[0] * (1.0f / (Ez - 1));
    float inv = 1.0f / (sqrtf(var) + 1e-8f);

    float4 gg = ((const float4*)g)[tid];
    float4 bb = ((const float4*)be)[tid];
    __half2 h0 = __floats2half2_rn(gg.x * dx * inv + bb.x, gg.y * dy * inv + bb.y);
    __half2 h1 = __floats2half2_rn(gg.z * dz * inv + bb.z, gg.w * dw * inv + bb.w);
    *(uint2*)(y + (size_t)row * Ez + tid * 4) = make_uint2(*(unsigned*)&h0, *(unsigned*)&h1);
}

// ---------------- FP16 tensor-core GEMM, cp.async 3-stage, ldmatrix, 2 CTA/SM ----------------
#define BM 128
#define BNt 128
#define BKh 64
#define STH 72      // half stride: 36 words == 4 mod 32 -> conflict-free
#define STAGES 3

#define GEMM_SMEM (STAGES*(BM+BNt)*STH*2)

template<int ACT, bool RES, bool HOUT, bool QSC>
__global__ __launch_bounds__(256, 2) void gemm_f16(const __half* __restrict__ A,
                                                   const __half* __restrict__ Bw,
                                                   const float* __restrict__ bias,
                                                   const float* __restrict__ res,
                                                   float* __restrict__ Cf,
                                                   __half* __restrict__ Ch,
                                                   int M, int N, int K)
{
    extern __shared__ __half smem[];
    __half* As = smem;                          // [STAGES][BM][STH]
    __half* Bs = smem + STAGES * BM * STH;      // [STAGES][BNt][STH]

    const int tid  = threadIdx.x;
    const int warp = tid >> 5, lane = tid & 31;
    const int wm = warp >> 1, wn = warp & 1;    // 4 x 2, warp tile 32x64
    const int qr = lane >> 2, qt = lane & 3;
    const int lane_r  = lane & 15;
    const int lane_c8 = (lane >> 4) * 8;
    const int rowBase = blockIdx.y * BM;
    const int colBase = blockIdx.x * BNt;

    float acc[2][8][4];
    #pragma unroll
    for (int mi = 0; mi < 2; mi++)
        #pragma unroll
        for (int ni = 0; ni < 8; ni++)
            #pragma unroll
            for (int r = 0; r < 4; r++) acc[mi][ni][r] = 0.0f;

    auto prefetch = [&](int k0, int buf) {
        __half* as = As + buf * BM * STH;
        __half* bs = Bs + buf * BNt * STH;
        #pragma unroll
        for (int l = 0; l < 4; l++) {
            int idx = l * 256 + tid;
            int r = idx >> 3, c = (idx & 7) * 8;
            cp_async16(as + r * STH + c, A + (size_t)(rowBase + r) * K + k0 + c);
        }
        #pragma unroll
        for (int l = 0; l < 4; l++) {
            int idx = l * 256 + tid;
            int r = idx >> 3, c = (idx & 7) * 8;
            cp_async16(bs + r * STH + c, Bw + (size_t)(colBase + r) * K + k0 + c);
        }
    };

    const int T = K / BKh;
    #pragma unroll
    for (int s = 0; s < STAGES - 1; s++) { prefetch(s * BKh, s); cp_commit(); }

    for (int t = 0; t < T; t++) {
        cp_wait<STAGES - 2>();
        __syncthreads();
        if (t + STAGES - 1 < T) prefetch((t + STAGES - 1) * BKh, (t + STAGES - 1) % STAGES);
        cp_commit();

        unsigned a_base = (unsigned)__cvta_generic_to_shared(
            As + (t % STAGES) * BM * STH + (wm * 32 + lane_r) * STH + lane_c8);
        unsigned b_base = (unsigned)__cvta_generic_to_shared(
            Bs + (t % STAGES) * BNt * STH + (wn * 64 + lane_r) * STH + lane_c8);

        #pragma unroll
        for (int kk = 0; kk < BKh; kk += 16) {
            unsigned af[2][4], bf[8][2];
            #pragma unroll
            for (int mi = 0; mi < 2; mi++)
                ldsm_x4(af[mi][0], af[mi][1], af[mi][2], af[mi][3],
                        a_base + (mi * 16 * STH + kk) * 2);
            #pragma unroll
            for (int nt = 0; nt < 4; nt++) {
                unsigned r0, r1, r2, r3;
                ldsm_x4(r0, r1, r2, r3, b_base + (nt * 16 * STH + kk) * 2);
                bf[nt*2][0] = r0; bf[nt*2][1] = r2;
                bf[nt*2+1][0] = r1; bf[nt*2+1][1] = r3;
            }
            #pragma unroll
            for (int mi = 0; mi < 2; mi++)
                #pragma unroll
                for (int ni = 0; ni < 8; ni++)
                    mma_f16(acc[mi][ni], af[mi], bf[ni]);
        }
    }

    // epilogue
    const float sc = (QSC && colBase < Ez) ? 0.125f : 1.0f;
    #pragma unroll
    for (int mi = 0; mi < 2; mi++) {
        int r0 = rowBase + wm * 32 + mi * 16 + qr;
        #pragma unroll
        for (int ni = 0; ni < 8; ni++) {
            int cc = colBase + wn * 64 + ni * 8 + qt * 2;
            float b0 = bias[cc], b1 = bias[cc + 1];
            float v0 = acc[mi][ni][0] + b0;
            float v1 = acc[mi][ni][1] + b1;
            float v2 = acc[mi][ni][2] + b0;
            float v3 = acc[mi][ni][3] + b1;
            if (RES) {
                v0 += res[(size_t)r0 * N + cc];
                v1 += res[(size_t)r0 * N + cc + 1];
                v2 += res[(size_t)(r0 + 8) * N + cc];
                v3 += res[(size_t)(r0 + 8) * N + cc + 1];
            }
            if (ACT == 1) { v0 = gelu_f(v0); v1 = gelu_f(v1); v2 = gelu_f(v2); v3 = gelu_f(v3); }
            if (QSC) { v0 *= sc; v1 *= sc; v2 *= sc; v3 *= sc; }
            if (HOUT) {
                __half2 h01 = __floats2half2_rn(v0, v1);
                __half2 h23 = __floats2half2_rn(v2, v3);
                *(unsigned*)(Ch + (size_t)r0 * N + cc)       = *(unsigned*)&h01;
                *(unsigned*)(Ch + (size_t)(r0 + 8) * N + cc) = *(unsigned*)&h23;
            } else {
                *(float2*)(Cf + (size_t)r0 * N + cc)       = make_float2(v0, v1);
                *(float2*)(Cf + (size_t)(r0 + 8) * N + cc) = make_float2(v2, v3);
            }
        }
    }
}

// ---------------- FP16 fused attention: 128-q rows/CTA, register-resident P ----------------
// grid (S/128, H, B), 8 warps; warp w owns q-rows w*16..w*16+15 end-to-end.
// QK^T C-fragment layout == PV A-fragment layout -> exp in regs, no P smem, no mid-chunk sync.
// Mask from packed bits (1 bit/entry). Masked score = -0.01 -> p = exp(-0.01) const.
#define AST 72
#define QKVS (3*Ez)
#define ATTN_SMEM ((128*AST + 2*64*AST + 2*64*AST) * 2)

__global__ __launch_bounds__(256, 2) void attn_mma(const __half* __restrict__ QKV,
                                                   const uint32_t* __restrict__ pk,
                                                   __half* __restrict__ O)
{
    extern __shared__ __half smh[];
    __half* Qs = smh;                   // [128][72]
    __half* Ks = smh + 128*AST;         // [2][64][72]
    __half* Vs = smh + 128*AST + 2*64*AST;

    const int qt_ = blockIdx.x, h = blockIdx.y, b = blockIdx.z;
    const int q0 = qt_ * 128;
    const int tid = threadIdx.x;
    const int warp = tid >> 5, lane = tid & 31;
    const int qr = lane >> 2, qt = lane & 3;
    const int lane_r  = lane & 15;
    const int lane_c8 = (lane >> 4) * 8;

    const __half* Qg = QKV + h * HDz;
    const __half* Kg = QKV + Ez + h * HDz;
    const __half* Vg = QKV + 2 * Ez + h * HDz;

    // Q tile: 128 rows x 8 chunks (group 0)
    #pragma unroll
    for (int l = 0; l < 4; l++) {
        int idx = l * 256 + tid;
        int r = idx >> 3, c = (idx & 7) * 8;
        cp_async16(Qs + r * AST + c, Qg + (size_t)(b*Sz + q0 + r) * QKVS + c);
    }
    cp_commit();

    auto prefetch = [&](int t, int buf) {
        int k0 = t * 64;
        #pragma unroll
        for (int l = 0; l < 2; l++) {
            int idx = l * 256 + tid;
            int r = idx >> 3, c = (idx & 7) * 8;
            cp_async16(Ks + buf*64*AST + r*AST + c, Kg + (size_t)(b*Sz + k0 + r) * QKVS + c);
            cp_async16(Vs + buf*64*AST + r*AST + c, Vg + (size_t)(b*Sz + k0 + r) * QKVS + c);
        }
    };

    prefetch(0, 0); cp_commit();

    // Q fragments -> registers (Q smem dead afterwards)
    cp_wait<1>();
    __syncthreads();
    unsigned qf[4][4];
    {
        unsigned qa = (unsigned)__cvta_generic_to_shared(Qs + (warp*16 + lane_r)*AST + lane_c8);
        #pragma unroll
        for (int k4 = 0; k4 < 4; k4++)
            ldsm_x4(qf[k4][0], qf[k4][1], qf[k4][2], qf[k4][3], qa + k4 * 32);
    }

    float acc[8][4];
    #pragma unroll
    for (int j = 0; j < 8; j++)
        #pragma unroll
        for (int r = 0; r < 4; r++) acc[j][r] = 0.0f;
    float rs0 = 0.f, rs1 = 0.f;
    const float EM = 0.99004983374916805f;   // exp(-0.01)

    const uint32_t* pk0 = pk + (size_t)(b*Sz + q0 + warp*16 + qr) * 32;
    const uint32_t* pk1 = pk0 + 8 * 32;

    for (int t = 0; t < Sz/64; t++) {
        int buf = t & 1;
        cp_wait<0>();
        __syncthreads();
        if (t + 1 < Sz/64) prefetch(t + 1, buf ^ 1);
        cp_commit();

        // mask words for this 64-col chunk (L2-resident, tiny)
        uint2 mw0 = *(const uint2*)(pk0 + t * 2);
        uint2 mw1 = *(const uint2*)(pk1 + t * 2);

        // ---- scores: 16 q-rows x 64 k-cols per warp ----
        unsigned kb = (unsigned)__cvta_generic_to_shared(
            Ks + buf*64*AST + lane_r*AST + lane_c8);
        float scs[8][4];
        #pragma unroll
        for (int j = 0; j < 8; j++)
            #pragma unroll
            for (int r = 0; r < 4; r++) scs[j][r] = 0.0f;

        #pragma unroll
        for (int k4 = 0; k4 < 4; k4++) {
            #pragma unroll
            for (int nt = 0; nt < 4; nt++) {
                unsigned r0, r1, r2, r3;
                ldsm_x4(r0, r1, r2, r3, kb + (nt * 16 * AST + k4 * 16) * 2);
                unsigned b0[2] = {r0, r2}, b1[2] = {r1, r3};
                mma_f16(scs[nt*2],   qf[k4], b0);
                mma_f16(scs[nt*2+1], qf[k4], b1);
            }
        }

        // ---- mask + exp in registers ----
        #pragma unroll
        for (int j = 0; j < 8; j++) {
            int cc = j * 8 + 2 * qt;
            unsigned w0 = (j < 4) ? mw0.x : mw0.y;
            unsigned w1 = (j < 4) ? mw1.x : mw1.y;
            int sh = cc & 31;
            float p00 = ((w0 >> sh) & 1u)       ? __expf(scs[j][0]) : EM;
            float p01 = ((w0 >> (sh+1)) & 1u)   ? __expf(scs[j][1]) : EM;
            float p10 = ((w1 >> sh) & 1u)       ? __expf(scs[j][2]) : EM;
            float p11 = ((w1 >> (sh+1)) & 1u)   ? __expf(scs[j][3]) : EM;
            rs0 += p00 + p01;
            rs1 += p10 + p11;
            scs[j][0] = p00; scs[j][1] = p01; scs[j][2] = p10; scs[j][3] = p11;
        }

        // ---- O += P * V (P fragments built from scs in place) ----
        unsigned vb = (unsigned)__cvta_generic_to_shared(
            Vs + buf*64*AST + lane_r*AST + lane_c8);
        #pragma unroll
        for (int j2 = 0; j2 < 4; j2++) {
            unsigned af[4];
            __half2 a0 = __floats2half2_rn(scs[2*j2][0],   scs[2*j2][1]);
            __half2 a1 = __floats2half2_rn(scs[2*j2][2],   scs[2*j2][3]);
            __half2 a2 = __floats2half2_rn(scs[2*j2+1][0], scs[2*j2+1][1]);
            __half2 a3 = __floats2half2_rn(scs[2*j2+1][2], scs[2*j2+1][3]);
            af[0] = *(unsigned*)&a0; af[1] = *(unsigned*)&a1;
            af[2] = *(unsigned*)&a2; af[3] = *(unsigned*)&a3;
            #pragma unroll
            for (int nt = 0; nt < 4; nt++) {
                unsigned r0, r1, r2, r3;
                ldsm_x4_t(r0, r1, r2, r3, vb + (j2 * 16 * AST + nt * 16) * 2);
                unsigned b0[2] = {r0, r1}, b1[2] = {r2, r3};
                mma_f16(acc[nt*2],   af, b0);
                mma_f16(acc[nt*2+1], af, b1);
            }
        }
        // no end-of-loop sync needed: next iteration's top syncthreads guards buffer reuse
    }

    // ---- row sums are warp-local: reduce over the 4 qt lanes ----
    rs0 += __shfl_xor_sync(0xffffffffu, rs0, 1);
    rs0 += __shfl_xor_sync(0xffffffffu, rs0, 2);
    rs1 += __shfl_xor_sync(0xffffffffu, rs1, 1);
    rs1 += __shfl_xor_sync(0xffffffffu, rs1, 2);
    float inv0 = 1.0f / rs0;
    float inv1 = 1.0f / rs1;

    // ---- write O (half; feeds Wo GEMM) ----
    const size_t row0 = (size_t)(b*Sz + q0 + warp*16 + qr);
    #pragma unroll
    for (int j = 0; j < 8; j++) {
        int cc = h*HDz + j*8 + 2*qt;
        __half2 h0 = __floats2half2_rn(acc[j][0] * inv0, acc[j][1] * inv0);
        __half2 h1 = __floats2half2_rn(acc[j][2] * inv1, acc[j][3] * inv1);
        *(unsigned*)(O + row0 * Ez + cc)       = *(unsigned*)&h0;
        *(unsigned*)(O + (row0 + 8) * Ez + cc) = *(unsigned*)&h1;
    }
}

// ---------------- launch ----------------
extern "C" void kernel_launch(void* const* d_in, const int* in_sizes, int n_in,
                              void* d_out, int out_size)
{
    const float* x   = (const float*)d_in[0];
    const int*   msk = (const int*)  d_in[1];
    const float* Wq  = (const float*)d_in[2];
    const float* bq  = (const float*)d_in[3];
    const float* Wk  = (const float*)d_in[4];
    const float* bk  = (const float*)d_in[5];
    const float* Wv  = (const float*)d_in[6];
    const float* bv  = (const float*)d_in[7];
    const float* Wo  = (const float*)d_in[8];
    const float* bo  = (const float*)d_in[9];
    const float* W1  = (const float*)d_in[10];
    const float* b1  = (const float*)d_in[11];
    const float* W2  = (const float*)d_in[12];
    const float* b2  = (const float*)d_in[13];
    const float* g1  = (const float*)d_in[14];
    const float* be1 = (const float*)d_in[15];
    const float* g2  = (const float*)d_in[16];
    const float* be2 = (const float*)d_in[17];
    float* out = (float*)d_out;

    __half *nx, *qkv, *o, *nx2, *h1, *wqkv, *wo, *w1, *w2;
    float *x1, *bqkv;
    uint32_t* pk;
    cudaGetSymbolAddress((void**)&nx,   g_nx);
    cudaGetSymbolAddress((void**)&qkv,  g_qkv);
    cudaGetSymbolAddress((void**)&o,    g_o);
    cudaGetSymbolAddress((void**)&x1,   g_x1);
    cudaGetSymbolAddress((void**)&nx2,  g_nx2);
    cudaGetSymbolAddress((void**)&h1,   g_h1);
    cudaGetSymbolAddress((void**)&wqkv, g_wqkv);
    cudaGetSymbolAddress((void**)&wo,   g_wo);
    cudaGetSymbolAddress((void**)&w1,   g_w1);
    cudaGetSymbolAddress((void**)&w2,   g_w2);
    cudaGetSymbolAddress((void**)&bqkv, g_bqkv);
    cudaGetSymbolAddress((void**)&pk,   g_pk);

    static cudaStream_t s1 = nullptr, s2 = nullptr;
    static cudaEvent_t ev0 = nullptr, ev1 = nullptr, ev2 = nullptr;
    static bool attr_done = false;
    if (!attr_done) {
        cudaFuncSetAttribute((const void*)gemm_f16<0,false,true,true>,   cudaFuncAttributeMaxDynamicSharedMemorySize, GEMM_SMEM);
        cudaFuncSetAttribute((const void*)gemm_f16<0,true,false,false>,  cudaFuncAttributeMaxDynamicSharedMemorySize, GEMM_SMEM);
        cudaFuncSetAttribute((const void*)gemm_f16<1,false,true,false>,  cudaFuncAttributeMaxDynamicSharedMemorySize, GEMM_SMEM);
        cudaFuncSetAttribute((const void*)attn_mma, cudaFuncAttributeMaxDynamicSharedMemorySize, ATTN_SMEM);
        cudaStreamCreateWithFlags(&s1, cudaStreamNonBlocking);
        cudaStreamCreateWithFlags(&s2, cudaStreamNonBlocking);
        cudaEventCreateWithFlags(&ev0, cudaEventDisableTiming);
        cudaEventCreateWithFlags(&ev1, cudaEventDisableTiming);
        cudaEventCreateWithFlags(&ev2, cudaEventDisableTiming);
        attr_done = true;
    }

    const int nE4 = Ez*Ez/4;
    const int nF4 = DFFz*Ez/4;

    cudaEventRecord(ev0, 0);

    // s1: pack mask + convert Wo/W1/W2 (overlaps LN1/QKV GEMM)
    cudaStreamWaitEvent(s1, ev0, 0);
    pack_mask<<<Mz, 256, 0, s1>>>(msk, pk);
    cvt_h<<<(nE4+255)/256, 256, 0, s1>>>(Wo, wo, nE4);
    cvt_h<<<(nF4+255)/256, 256, 0, s1>>>(W1, w1, nF4);
    cvt_h<<<(nF4+255)/256, 256, 0, s1>>>(W2, w2, nF4);
    cudaEventRecord(ev1, s1);

    // s2: QKV weights + bias (overlaps LN1)
    cudaStreamWaitEvent(s2, ev0, 0);
    cvt_h<<<(nE4+255)/256, 256, 0, s2>>>(Wq, wqkv,           nE4);
    cvt_h<<<(nE4+255)/256, 256, 0, s2>>>(Wk, wqkv + Ez*Ez,   nE4);
    cvt_h<<<(nE4+255)/256, 256, 0, s2>>>(Wv, wqkv + 2*Ez*Ez, nE4);
    bias3_kernel<<<4, 256, 0, s2>>>(bq, bk, bv, bqkv);
    cudaEventRecord(ev2, s2);

    dim3 gQKV(3*Ez/BNt, Mz/BM);   // (24, 32)
    dim3 gE(Ez/BNt,     Mz/BM);   // (8, 32)
    dim3 gF(DFFz/BNt,   Mz/BM);   // (32, 32)

    // 1) LN1 (half output)
    ln_kernel<<<Mz, 256>>>(x, g1, be1, nx);
    // join QKV weights
    cudaStreamWaitEvent(0, ev2, 0);
    // 2) fused QKV projection (q pre-scaled by 0.125)
    gemm_f16<0,false,true,true><<<gQKV, 256, GEMM_SMEM>>>(nx, wqkv, bqkv, nullptr, nullptr, qkv, Mz, 3*Ez, Ez);
    // join packed mask + Wo/W1/W2
    cudaStreamWaitEvent(0, ev1, 0);
    // 3) attention (128 q-rows per CTA, register P)
    attn_mma<<<dim3(Sz/128, Hz, Bz), 256, ATTN_SMEM>>>(qkv, pk, o);
    // 4) output projection + residual (fp32 out)
    gemm_f16<0,true,false,false><<<gE, 256, GEMM_SMEM>>>(o, wo, bo, x, x1, nullptr, Mz, Ez, Ez);
    // 5) LN2 (half output)
    ln_kernel<<<Mz, 256>>>(x1, g2, be2, nx2);
    // 6) FFN up + GELU (half out)
    gemm_f16<1,false,true,false><<<gF, 256, GEMM_SMEM>>>(nx2, w1, b1, nullptr, nullptr, h1, Mz, DFFz, Ez);
    // 7) FFN down + residual -> out (fp32)
    gemm_f16<0,true,false,false><<<gE, 256, GEMM_SMEM>>>(h1, w2, b2, x1, out, nullptr, Mz, Ez, DFFz);
}

// round 16
// speedup vs baseline: 7.2910x; 1.0138x over previous
#include <cuda_runtime.h>
#include <cuda_fp16.h>
#include <math.h>
#include <cstdint>

// Shapes (fixed)
#define Bz 4
#define Sz 1024
#define Ez 1024
#define Hz 16
#define HDz 64
#define DFFz 4096
#define Mz (Bz*Sz)   // 4096 rows of activations
#define MH (Mz/2)    // half-batch chunk (2048 rows)

// ---------------- scratch (device globals; no allocations) ----------------
__device__ __half g_nx  [Mz*Ez];
__device__ __half g_qkv [(size_t)Mz*3*Ez];
__device__ __half g_o   [Mz*Ez];
__device__ float  g_x1  [Mz*Ez];
__device__ __half g_nx2 [Mz*Ez];
__device__ __half g_h1  [(size_t)Mz*DFFz];
__device__ __half g_wqkv[3*Ez*Ez];
__device__ __half g_wo  [Ez*Ez];
__device__ __half g_w1  [(size_t)DFFz*Ez];
__device__ __half g_w2  [(size_t)Ez*DFFz];
__device__ float  g_bqkv[3*Ez];
__device__ uint32_t g_pk[Mz*32];      // packed mask bits: [B*S][S/32]

// ---------------- helpers ----------------
__device__ __forceinline__ float gelu_f(float x) {
    const float c = 0.7978845608028654f; // sqrt(2/pi)
    float u = c * (x + 0.044715f * x * x * x);
    return 0.5f * x * (1.0f + tanhf(u));
}

__device__ __forceinline__ void mma_f16(float* c, const unsigned* a, const unsigned* b) {
    asm volatile(
        "mma.sync.aligned.m16n8k16.row.col.f32.f16.f16.f32 "
        "{%0,%1,%2,%3}, {%4,%5,%6,%7}, {%8,%9}, {%0,%1,%2,%3};\n"
        : "+f"(c[0]), "+f"(c[1]), "+f"(c[2]), "+f"(c[3])
        : "r"(a[0]), "r"(a[1]), "r"(a[2]), "r"(a[3]),
          "r"(b[0]), "r"(b[1]));
}

__device__ __forceinline__ void ldsm_x4(unsigned& r0, unsigned& r1, unsigned& r2, unsigned& r3, unsigned addr) {
    asm volatile("ldmatrix.sync.aligned.m8n8.x4.shared.b16 {%0,%1,%2,%3}, [%4];\n"
                 : "=r"(r0), "=r"(r1), "=r"(r2), "=r"(r3) : "r"(addr));
}
__device__ __forceinline__ void ldsm_x4_t(unsigned& r0, unsigned& r1, unsigned& r2, unsigned& r3, unsigned addr) {
    asm volatile("ldmatrix.sync.aligned.m8n8.x4.trans.shared.b16 {%0,%1,%2,%3}, [%4];\n"
                 : "=r"(r0), "=r"(r1), "=r"(r2), "=r"(r3) : "r"(addr));
}

__device__ __forceinline__ void cp_async16(void* sdst, const void* gsrc) {
    unsigned s = (unsigned)__cvta_generic_to_shared(sdst);
    asm volatile("cp.async.cg.shared.global [%0], [%1], 16;\n" :: "r"(s), "l"(gsrc));
}
__device__ __forceinline__ void cp_commit() {
    asm volatile("cp.async.commit_group;\n" ::);
}
template<int N>
__device__ __forceinline__ void cp_wait() {
    asm volatile("cp.async.wait_group %0;\n" :: "n"(N));
}

// ---------------- fp32 -> fp16 conversion (weights) ----------------
__global__ __launch_bounds__(256) void cvt_h(const float* __restrict__ in,
                                             __half* __restrict__ out, int n4)
{
    int i = blockIdx.x * 256 + threadIdx.x;
    if (i < n4) {
        float4 v = ((const float4*)in)[i];
        __half2 h0 = __floats2half2_rn(v.x, v.y);
        __half2 h1 = __floats2half2_rn(v.z, v.w);
        *(uint2*)(out + (size_t)i * 4) = make_uint2(*(unsigned*)&h0, *(unsigned*)&h1);
    }
}

__global__ __launch_bounds__(256) void bias3_kernel(const float* __restrict__ a,
                                                    const float* __restrict__ b,
                                                    const float* __restrict__ c,
                                                    float* __restrict__ o)
{
    int i = blockIdx.x * 256 + threadIdx.x;
    if (i < Ez) { o[i] = a[i]; o[i + Ez] = b[i]; o[i + 2*Ez] = c[i]; }
}

// ---------------- pack mask to bits (1 = keep score, 0 = use -0.01) ----------------
__global__ __launch_bounds__(256) void pack_mask(const int* __restrict__ mask,
                                                 uint32_t* __restrict__ pk)
{
    int row = blockIdx.x;                  // b*S + q
    int lane = threadIdx.x & 31, w = threadIdx.x >> 5;   // 8 warps
    const int* mrow = mask + (size_t)row * Sz;
    #pragma unroll
    for (int it = 0; it < 4; it++) {
        int word = it * 8 + w;
        int v = mrow[word * 32 + lane];
        unsigned bits = __ballot_sync(0xffffffffu, v != 0);
        if (lane == 0) pk[row * 32 + word] = bits;
    }
}

// ---------------- LayerNorm (ddof=1, eps added to std); half output ----------------
__global__ __launch_bounds__(256) void ln_kernel(const float* __restrict__ x,
                                                 const float* __restrict__ g,
                                                 const float* __restrict__ be,
                                                 __half* __restrict__ y)
{
    __shared__ float red[32];
    int row = blockIdx.x;
    int tid = threadIdx.x;
    const float4* xr = (const float4*)(x + (size_t)row * Ez);
    float4 v = xr[tid];

    float s = v.x + v.y + v.z + v.w;
    #pragma unroll
    for (int o = 16; o > 0; o >>= 1) s += __shfl_xor_sync(0xffffffffu, s, o);
    if ((tid & 31) == 0) red[tid >> 5] = s;
    __syncthreads();
    float t = (tid < 8) ? red[tid] : 0.0f;
    if (tid < 32) {
        #pragma unroll
        for (int o = 4; o > 0; o >>= 1) t += __shfl_xor_sync(0xffffffffu, t, o);
        if (tid == 0) red[0] = t;
    }
    __syncthreads();
    float mean = red[0] * (1.0f / Ez);
    __syncthreads();

    float dx = v.x - mean, dy = v.y - mean, dz = v.z - mean, dw = v.w - mean;
    float sq = dx*dx + dy*dy + dz*dz + dw*dw;
    #pragma unroll
    for (int o = 16; o > 0; o >>= 1) sq += __shfl_xor_sync(0xffffffffu, sq, o);
    if ((tid & 31) == 0) red[tid >> 5] = sq;
    __syncthreads();
    float t2 = (tid < 8) ? red[tid] : 0.0f;
    if (tid < 32) {
        #pragma unroll
        for (int o = 4; o > 0; o >>= 1) t2 += __shfl_xor_sync(0xffffffffu, t2, o);
        if (tid == 0) red[0] = t2;
    }
    __syncthreads();
    float var = red[0] * (1.0f / (Ez - 1));
    float inv = 1.0f / (sqrtf(var) + 1e-8f);

    float4 gg = ((const float4*)g)[tid];
    float4 bb = ((const float4*)be)[tid];
    __half2 h0 = __floats2half2_rn(gg.x * dx * inv + bb.x, gg.y * dy * inv + bb.y);
    __half2 h1 = __floats2half2_rn(gg.z * dz * inv + bb.z, gg.w * dw * inv + bb.w);
    *(uint2*)(y + (size_t)row * Ez + tid * 4) = make_uint2(*(unsigned*)&h0, *(unsigned*)&h1);
}

// ---------------- FP16 tensor-core GEMM, cp.async 3-stage, ldmatrix, 2 CTA/SM ----------------
#define BM 128
#define BNt 128
#define BKh 64
#define STH 72      // half stride: 36 words == 4 mod 32 -> conflict-free
#define STAGES 3

#define GEMM_SMEM (STAGES*(BM+BNt)*STH*2)

template<int ACT, bool RES, bool HOUT, bool QSC>
__global__ __launch_bounds__(256, 2) void gemm_f16(const __half* __restrict__ A,
                                                   const __half* __restrict__ Bw,
                                                   const float* __restrict__ bias,
                                                   const float* __restrict__ res,
                                                   float* __restrict__ Cf,
                                                   __half* __restrict__ Ch,
                                                   int M, int N, int K)
{
    extern __shared__ __half smem[];
    __half* As = smem;                          // [STAGES][BM][STH]
    __half* Bs = smem + STAGES * BM * STH;      // [STAGES][BNt][STH]

    const int tid  = threadIdx.x;
    const int warp = tid >> 5, lane = tid & 31;
    const int wm = warp >> 1, wn = warp & 1;    // 4 x 2, warp tile 32x64
    const int qr = lane >> 2, qt = lane & 3;
    const int lane_r  = lane & 15;
    const int lane_c8 = (lane >> 4) * 8;
    const int rowBase = blockIdx.y * BM;
    const int colBase = blockIdx.x * BNt;

    float acc[2][8][4];
    #pragma unroll
    for (int mi = 0; mi < 2; mi++)
        #pragma unroll
        for (int ni = 0; ni < 8; ni++)
            #pragma unroll
            for (int r = 0; r < 4; r++) acc[mi][ni][r] = 0.0f;

    auto prefetch = [&](int k0, int buf) {
        __half* as = As + buf * BM * STH;
        __half* bs = Bs + buf * BNt * STH;
        #pragma unroll
        for (int l = 0; l < 4; l++) {
            int idx = l * 256 + tid;
            int r = idx >> 3, c = (idx & 7) * 8;
            cp_async16(as + r * STH + c, A + (size_t)(rowBase + r) * K + k0 + c);
        }
        #pragma unroll
        for (int l = 0; l < 4; l++) {
            int idx = l * 256 + tid;
            int r = idx >> 3, c = (idx & 7) * 8;
            cp_async16(bs + r * STH + c, Bw + (size_t)(colBase + r) * K + k0 + c);
        }
    };

    const int T = K / BKh;
    #pragma unroll
    for (int s = 0; s < STAGES - 1; s++) { prefetch(s * BKh, s); cp_commit(); }

    for (int t = 0; t < T; t++) {
        cp_wait<STAGES - 2>();
        __syncthreads();
        if (t + STAGES - 1 < T) prefetch((t + STAGES - 1) * BKh, (t + STAGES - 1) % STAGES);
        cp_commit();

        unsigned a_base = (unsigned)__cvta_generic_to_shared(
            As + (t % STAGES) * BM * STH + (wm * 32 + lane_r) * STH + lane_c8);
        unsigned b_base = (unsigned)__cvta_generic_to_shared(
            Bs + (t % STAGES) * BNt * STH + (wn * 64 + lane_r) * STH + lane_c8);

        #pragma unroll
        for (int kk = 0; kk < BKh; kk += 16) {
            unsigned af[2][4], bf[8][2];
            #pragma unroll
            for (int mi = 0; mi < 2; mi++)
                ldsm_x4(af[mi][0], af[mi][1], af[mi][2], af[mi][3],
                        a_base + (mi * 16 * STH + kk) * 2);
            #pragma unroll
            for (int nt = 0; nt < 4; nt++) {
                unsigned r0, r1, r2, r3;
                ldsm_x4(r0, r1, r2, r3, b_base + (nt * 16 * STH + kk) * 2);
                bf[nt*2][0] = r0; bf[nt*2][1] = r2;
                bf[nt*2+1][0] = r1; bf[nt*2+1][1] = r3;
            }
            #pragma unroll
            for (int mi = 0; mi < 2; mi++)
                #pragma unroll
                for (int ni = 0; ni < 8; ni++)
                    mma_f16(acc[mi][ni], af[mi], bf[ni]);
        }
    }

    // epilogue
    const float sc = (QSC && colBase < Ez) ? 0.125f : 1.0f;
    #pragma unroll
    for (int mi = 0; mi < 2; mi++) {
        int r0 = rowBase + wm * 32 + mi * 16 + qr;
        #pragma unroll
        for (int ni = 0; ni < 8; ni++) {
            int cc = colBase + wn * 64 + ni * 8 + qt * 2;
            float b0 = bias[cc], b1 = bias[cc + 1];
            float v0 = acc[mi][ni][0] + b0;
            float v1 = acc[mi][ni][1] + b1;
            float v2 = acc[mi][ni][2] + b0;
            float v3 = acc[mi][ni][3] + b1;
            if (RES) {
                v0 += res[(size_t)r0 * N + cc];
                v1 += res[(size_t)r0 * N + cc + 1];
                v2 += res[(size_t)(r0 + 8) * N + cc];
                v3 += res[(size_t)(r0 + 8) * N + cc + 1];
            }
            if (ACT == 1) { v0 = gelu_f(v0); v1 = gelu_f(v1); v2 = gelu_f(v2); v3 = gelu_f(v3); }
            if (QSC) { v0 *= sc; v1 *= sc; v2 *= sc; v3 *= sc; }
            if (HOUT) {
                __half2 h01 = __floats2half2_rn(v0, v1);
                __half2 h23 = __floats2half2_rn(v2, v3);
                *(unsigned*)(Ch + (size_t)r0 * N + cc)       = *(unsigned*)&h01;
                *(unsigned*)(Ch + (size_t)(r0 + 8) * N + cc) = *(unsigned*)&h23;
            } else {
                *(float2*)(Cf + (size_t)r0 * N + cc)       = make_float2(v0, v1);
                *(float2*)(Cf + (size_t)(r0 + 8) * N + cc) = make_float2(v2, v3);
            }
        }
    }
}

// ---------------- FP16 fused attention: 128-q rows/CTA, register-resident P ----------------
// QKV/O are BASE pointers; b0 selects the batch range (global row index b*Sz+q).
#define AST 72
#define QKVS (3*Ez)
#define ATTN_SMEM ((128*AST + 2*64*AST + 2*64*AST) * 2)

__global__ __launch_bounds__(256, 2) void attn_mma(const __half* __restrict__ QKV,
                                                   const uint32_t* __restrict__ pk,
                                                   __half* __restrict__ O, int b0)
{
    extern __shared__ __half smh[];
    __half* Qs = smh;                   // [128][72]
    __half* Ks = smh + 128*AST;         // [2][64][72]
    __half* Vs = smh + 128*AST + 2*64*AST;

    const int qt_ = blockIdx.x, h = blockIdx.y, b = blockIdx.z + b0;
    const int q0 = qt_ * 128;
    const int tid = threadIdx.x;
    const int warp = tid >> 5, lane = tid & 31;
    const int qr = lane >> 2, qt = lane & 3;
    const int lane_r  = lane & 15;
    const int lane_c8 = (lane >> 4) * 8;

    const __half* Qg = QKV + h * HDz;
    const __half* Kg = QKV + Ez + h * HDz;
    const __half* Vg = QKV + 2 * Ez + h * HDz;

    #pragma unroll
    for (int l = 0; l < 4; l++) {
        int idx = l * 256 + tid;
        int r = idx >> 3, c = (idx & 7) * 8;
        cp_async16(Qs + r * AST + c, Qg + (size_t)(b*Sz + q0 + r) * QKVS + c);
    }
    cp_commit();

    auto prefetch = [&](int t, int buf) {
        int k0 = t * 64;
        #pragma unroll
        for (int l = 0; l < 2; l++) {
            int idx = l * 256 + tid;
            int r = idx >> 3, c = (idx & 7) * 8;
            cp_async16(Ks + buf*64*AST + r*AST + c, Kg + (size_t)(b*Sz + k0 + r) * QKVS + c);
            cp_async16(Vs + buf*64*AST + r*AST + c, Vg + (size_t)(b*Sz + k0 + r) * QKVS + c);
        }
    };

    prefetch(0, 0); cp_commit();

    cp_wait<1>();
    __syncthreads();
    unsigned qf[4][4];
    {
        unsigned qa = (unsigned)__cvta_generic_to_shared(Qs + (warp*16 + lane_r)*AST + lane_c8);
        #pragma unroll
        for (int k4 = 0; k4 < 4; k4++)
            ldsm_x4(qf[k4][0], qf[k4][1], qf[k4][2], qf[k4][3], qa + k4 * 32);
    }

    float acc[8][4];
    #pragma unroll
    for (int j = 0; j < 8; j++)
        #pragma unroll
        for (int r = 0; r < 4; r++) acc[j][r] = 0.0f;
    float rs0 = 0.f, rs1 = 0.f;
    const float EM = 0.99004983374916805f;   // exp(-0.01)

    const uint32_t* pk0 = pk + (size_t)(b*Sz + q0 + warp*16 + qr) * 32;
    const uint32_t* pk1 = pk0 + 8 * 32;

    for (int t = 0; t < Sz/64; t++) {
        int buf = t & 1;
        cp_wait<0>();
        __syncthreads();
        if (t + 1 < Sz/64) prefetch(t + 1, buf ^ 1);
        cp_commit();

        uint2 mw0 = *(const uint2*)(pk0 + t * 2);
        uint2 mw1 = *(const uint2*)(pk1 + t * 2);

        unsigned kb = (unsigned)__cvta_generic_to_shared(
            Ks + buf*64*AST + lane_r*AST + lane_c8);
        float scs[8][4];
        #pragma unroll
        for (int j = 0; j < 8; j++)
            #pragma unroll
            for (int r = 0; r < 4; r++) scs[j][r] = 0.0f;

        #pragma unroll
        for (int k4 = 0; k4 < 4; k4++) {
            #pragma unroll
            for (int nt = 0; nt < 4; nt++) {
                unsigned r0, r1, r2, r3;
                ldsm_x4(r0, r1, r2, r3, kb + (nt * 16 * AST + k4 * 16) * 2);
                unsigned b0f[2] = {r0, r2}, b1f[2] = {r1, r3};
                mma_f16(scs[nt*2],   qf[k4], b0f);
                mma_f16(scs[nt*2+1], qf[k4], b1f);
            }
        }

        #pragma unroll
        for (int j = 0; j < 8; j++) {
            int cc = j * 8 + 2 * qt;
            unsigned w0 = (j < 4) ? mw0.x : mw0.y;
            unsigned w1 = (j < 4) ? mw1.x : mw1.y;
            int sh = cc & 31;
            float p00 = ((w0 >> sh) & 1u)       ? __expf(scs[j][0]) : EM;
            float p01 = ((w0 >> (sh+1)) & 1u)   ? __expf(scs[j][1]) : EM;
            float p10 = ((w1 >> sh) & 1u)       ? __expf(scs[j][2]) : EM;
            float p11 = ((w1 >> (sh+1)) & 1u)   ? __expf(scs[j][3]) : EM;
            rs0 += p00 + p01;
            rs1 += p10 + p11;
            scs[j][0] = p00; scs[j][1] = p01; scs[j][2] = p10; scs[j][3] = p11;
        }

        unsigned vb = (unsigned)__cvta_generic_to_shared(
            Vs + buf*64*AST + lane_r*AST + lane_c8);
        #pragma unroll
        for (int j2 = 0; j2 < 4; j2++) {
            unsigned af[4];
            __half2 a0 = __floats2half2_rn(scs[2*j2][0],   scs[2*j2][1]);
            __half2 a1 = __floats2half2_rn(scs[2*j2][2],   scs[2*j2][3]);
            __half2 a2 = __floats2half2_rn(scs[2*j2+1][0], scs[2*j2+1][1]);
            __half2 a3 = __floats2half2_rn(scs[2*j2+1][2], scs[2*j2+1][3]);
            af[0] = *(unsigned*)&a0; af[1] = *(unsigned*)&a1;
            af[2] = *(unsigned*)&a2; af[3] = *(unsigned*)&a3;
            #pragma unroll
            for (int nt = 0; nt < 4; nt++) {
                unsigned r0, r1, r2, r3;
                ldsm_x4_t(r0, r1, r2, r3, vb + (j2 * 16 * AST + nt * 16) * 2);
                unsigned b0f[2] = {r0, r1}, b1f[2] = {r2, r3};
                mma_f16(acc[nt*2],   af, b0f);
                mma_f16(acc[nt*2+1], af, b1f);
            }
        }
    }

    rs0 += __shfl_xor_sync(0xffffffffu, rs0, 1);
    rs0 += __shfl_xor_sync(0xffffffffu, rs0, 2);
    rs1 += __shfl_xor_sync(0xffffffffu, rs1, 1);
    rs1 += __shfl_xor_sync(0xffffffffu, rs1, 2);
    float inv0 = 1.0f / rs0;
    float inv1 = 1.0f / rs1;

    const size_t row0 = (size_t)(b*Sz + q0 + warp*16 + qr);
    #pragma unroll
    for (int j = 0; j < 8; j++) {
        int cc = h*HDz + j*8 + 2*qt;
        __half2 h0 = __floats2half2_rn(acc[j][0] * inv0, acc[j][1] * inv0);
        __half2 h1 = __floats2half2_rn(acc[j][2] * inv1, acc[j][3] * inv1);
        *(unsigned*)(O + row0 * Ez + cc)       = *(unsigned*)&h0;
        *(unsigned*)(O + (row0 + 8) * Ez + cc) = *(unsigned*)&h1;
    }
}

// ---------------- launch ----------------
extern "C" void kernel_launch(void* const* d_in, const int* in_sizes, int n_in,
                              void* d_out, int out_size)
{
    const float* x   = (const float*)d_in[0];
    const int*   msk = (const int*)  d_in[1];
    const float* Wq  = (const float*)d_in[2];
    const float* bq  = (const float*)d_in[3];
    const float* Wk  = (const float*)d_in[4];
    const float* bk  = (const float*)d_in[5];
    const float* Wv  = (const float*)d_in[6];
    const float* bv  = (const float*)d_in[7];
    const float* Wo  = (const float*)d_in[8];
    const float* bo  = (const float*)d_in[9];
    const float* W1  = (const float*)d_in[10];
    const float* b1  = (const float*)d_in[11];
    const float* W2  = (const float*)d_in[12];
    const float* b2  = (const float*)d_in[13];
    const float* g1  = (const float*)d_in[14];
    const float* be1 = (const float*)d_in[15];
    const float* g2  = (const float*)d_in[16];
    const float* be2 = (const float*)d_in[17];
    float* out = (float*)d_out;

    __half *nx, *qkv, *o, *nx2, *h1, *wqkv, *wo, *w1, *w2;
    float *x1, *bqkv;
    uint32_t* pk;
    cudaGetSymbolAddress((void**)&nx,   g_nx);
    cudaGetSymbolAddress((void**)&qkv,  g_qkv);
    cudaGetSymbolAddress((void**)&o,    g_o);
    cudaGetSymbolAddress((void**)&x1,   g_x1);
    cudaGetSymbolAddress((void**)&nx2,  g_nx2);
    cudaGetSymbolAddress((void**)&h1,   g_h1);
    cudaGetSymbolAddress((void**)&wqkv, g_wqkv);
    cudaGetSymbolAddress((void**)&wo,   g_wo);
    cudaGetSymbolAddress((void**)&w1,   g_w1);
    cudaGetSymbolAddress((void**)&w2,   g_w2);
    cudaGetSymbolAddress((void**)&bqkv, g_bqkv);
    cudaGetSymbolAddress((void**)&pk,   g_pk);

    static cudaStream_t s1 = nullptr, s2 = nullptr, sB = nullptr;
    static cudaEvent_t ev0 = nullptr, ev1 = nullptr, ev2 = nullptr;
    static cudaEvent_t evQB = nullptr, evB = nullptr;
    static bool attr_done = false;
    if (!attr_done) {
        cudaFuncSetAttribute((const void*)gemm_f16<0,false,true,true>,   cudaFuncAttributeMaxDynamicSharedMemorySize, GEMM_SMEM);
        cudaFuncSetAttribute((const void*)gemm_f16<0,true,false,false>,  cudaFuncAttributeMaxDynamicSharedMemorySize, GEMM_SMEM);
        cudaFuncSetAttribute((const void*)gemm_f16<1,false,true,false>,  cudaFuncAttributeMaxDynamicSharedMemorySize, GEMM_SMEM);
        cudaFuncSetAttribute((const void*)attn_mma, cudaFuncAttributeMaxDynamicSharedMemorySize, ATTN_SMEM);
        cudaStreamCreateWithFlags(&s1, cudaStreamNonBlocking);
        cudaStreamCreateWithFlags(&s2, cudaStreamNonBlocking);
        cudaStreamCreateWithFlags(&sB, cudaStreamNonBlocking);
        cudaEventCreateWithFlags(&ev0,  cudaEventDisableTiming);
        cudaEventCreateWithFlags(&ev1,  cudaEventDisableTiming);
        cudaEventCreateWithFlags(&ev2,  cudaEventDisableTiming);
        cudaEventCreateWithFlags(&evQB, cudaEventDisableTiming);
        cudaEventCreateWithFlags(&evB,  cudaEventDisableTiming);
        attr_done = true;
    }

    const int nE4 = Ez*Ez/4;
    const int nF4 = DFFz*Ez/4;

    cudaEventRecord(ev0, 0);

    // s1: pack mask + convert Wo/W1/W2 (overlaps LN1/QKV GEMMs)
    cudaStreamWaitEvent(s1, ev0, 0);
    pack_mask<<<Mz, 256, 0, s1>>>(msk, pk);
    cvt_h<<<(nE4+255)/256, 256, 0, s1>>>(Wo, wo, nE4);
    cvt_h<<<(nF4+255)/256, 256, 0, s1>>>(W1, w1, nF4);
    cvt_h<<<(nF4+255)/256, 256, 0, s1>>>(W2, w2, nF4);
    cudaEventRecord(ev1, s1);

    // s2: QKV weights + bias (overlaps LN1)
    cudaStreamWaitEvent(s2, ev0, 0);
    cvt_h<<<(nE4+255)/256, 256, 0, s2>>>(Wq, wqkv,           nE4);
    cvt_h<<<(nE4+255)/256, 256, 0, s2>>>(Wk, wqkv + Ez*Ez,   nE4);
    cvt_h<<<(nE4+255)/256, 256, 0, s2>>>(Wv, wqkv + 2*Ez*Ez, nE4);
    bias3_kernel<<<4, 256, 0, s2>>>(bq, bk, bv, bqkv);
    cudaEventRecord(ev2, s2);

    // chunk geometry (half batches: rows [0,2048) and [2048,4096))
    dim3 gQKVh(3*Ez/BNt, MH/BM);   // (24, 16)
    dim3 gEh(Ez/BNt,     MH/BM);   // (8, 16)
    dim3 gFh(DFFz/BNt,   MH/BM);   // (32, 16)
    const size_t offE = (size_t)MH * Ez;
    const size_t offQ = (size_t)MH * 3*Ez;
    const size_t offF = (size_t)MH * DFFz;

    // main: LN1 full, then QKV_A, QKV_B serialized (B's QKV overlaps A's attention)
    ln_kernel<<<Mz, 256>>>(x, g1, be1, nx);
    cudaStreamWaitEvent(0, ev2, 0);
    gemm_f16<0,false,true,true><<<gQKVh, 256, GEMM_SMEM>>>(nx, wqkv, bqkv, nullptr, nullptr, qkv, MH, 3*Ez, Ez);
    gemm_f16<0,false,true,true><<<gQKVh, 256, GEMM_SMEM>>>(nx + offE, wqkv, bqkv, nullptr, nullptr, qkv + offQ, MH, 3*Ez, Ez);
    cudaEventRecord(evQB, 0);

    // chain B on side stream sB: attn_B -> Wo_B -> LN2_B -> FFN1_B -> FFN2_B
    // NOTE: attn gets BASE pointers (qkv, o); b0=2 provides the global batch offset.
    cudaStreamWaitEvent(sB, evQB, 0);
    cudaStreamWaitEvent(sB, ev1, 0);
    attn_mma<<<dim3(Sz/128, Hz, 2), 256, ATTN_SMEM, sB>>>(qkv, pk, o, 2);
    gemm_f16<0,true,false,false><<<gEh, 256, GEMM_SMEM, sB>>>(o + offE, wo, bo, x + offE, x1 + offE, nullptr, MH, Ez, Ez);
    ln_kernel<<<MH, 256, 0, sB>>>(x1 + offE, g2, be2, nx2 + offE);
    gemm_f16<1,false,true,false><<<gFh, 256, GEMM_SMEM, sB>>>(nx2 + offE, w1, b1, nullptr, nullptr, h1 + offF, MH, DFFz, Ez);
    gemm_f16<0,true,false,false><<<gEh, 256, GEMM_SMEM, sB>>>(h1 + offF, w2, b2, x1 + offE, out + offE, nullptr, MH, Ez, DFFz);
    cudaEventRecord(evB, sB);

    // chain A on main: attn_A -> Wo_A -> LN2_A -> FFN1_A -> FFN2_A
    cudaStreamWaitEvent(0, ev1, 0);
    attn_mma<<<dim3(Sz/128, Hz, 2), 256, ATTN_SMEM>>>(qkv, pk, o, 0);
    gemm_f16<0,true,false,false><<<gEh, 256, GEMM_SMEM>>>(o, wo, bo, x, x1, nullptr, MH, Ez, Ez);
    ln_kernel<<<MH, 256>>>(x1, g2, be2, nx2);
    gemm_f16<1,false,true,false><<<gFh, 256, GEMM_SMEM>>>(nx2, w1, b1, nullptr, nullptr, h1, Mz/2, DFFz, Ez);
    gemm_f16<0,true,false,false><<<gEh, 256, GEMM_SMEM>>>(h1, w2, b2, x1, out, nullptr, MH, Ez, DFFz);

    // join chain B
    cudaStreamWaitEvent(0, evB, 0);
}